// round 12
// baseline (speedup 1.0000x reference)
#include <cuda_runtime.h>
#include <cuda_fp16.h>
#include <cstdint>

// Problem constants
#define Bn 4
#define Sn 2048
#define En 1024
#define Hn 16
#define Dn 64
#define BHn (Bn*Hn)     // 64
#define Mn  (Bn*Sn)     // 8192
#define NTOT 3072       // 3 projections * H * D

// GEMM tile config: block 128x128, 8 warps of 64x32, GBK=64
#define GBM 128
#define GBN 128
#define GBK 64
#define NC (En/GBK)     // 16 k-chunks
#define GP 72           // gemm smem row stride (halves)

// Attention smem row stride
#define HPAD 72
#define KVH (64 * HPAD)

// Scratch (allocation-free rule: __device__ globals)
__device__ __align__(256) __half g_Qh [(size_t)BHn * Sn * Dn];  // 16 MB
__device__ __align__(256) __half g_Kh [(size_t)BHn * Sn * Dn];  // 16 MB
__device__ __align__(256) __half g_Vth[(size_t)BHn * Dn * Sn];  // 16 MB (d-major)
__device__ __align__(256) __half g_ctxh[(size_t)Mn * En];       // 16 MB
__device__ __align__(256) __half g_xh [(size_t)Mn * En];        // 16 MB
__device__ __align__(256) __half g_Wth[(size_t)NTOT * En];      // 6 MB (K-major)
__device__ __align__(256) __half g_Woh[(size_t)En * En];        // 2 MB
__device__ __align__(256) float  g_bias[NTOT];

// ---------------------------------------------------------------------------
// Helpers
// ---------------------------------------------------------------------------
__device__ __forceinline__ uint32_t smem_u32(const void* p) {
    return (uint32_t)__cvta_generic_to_shared(p);
}
__device__ __forceinline__ void cp16(uint32_t dst, const void* src) {
    asm volatile("cp.async.cg.shared.global [%0], [%1], 16;" :: "r"(dst), "l"(src));
}
#define CP_COMMIT() asm volatile("cp.async.commit_group;" ::: "memory")
#define CP_WAIT1()  asm volatile("cp.async.wait_group 1;" ::: "memory")
#define CP_WAIT0()  asm volatile("cp.async.wait_group 0;" ::: "memory")

__device__ __forceinline__ uint32_t ldh2(const __half* p) {
    return *(const uint32_t*)p;
}
__device__ __forceinline__ uint32_t packh2(float lo, float hi) {
    __half2 h = __floats2half2_rn(lo, hi);
    return *(uint32_t*)&h;
}

// m16n8k16 fp16 MMA, fp32 accum (layout validated rounds 5-8)
__device__ __forceinline__ void mma16(float* c, const uint32_t* a, const uint32_t* b) {
    asm volatile("mma.sync.aligned.m16n8k16.row.col.f32.f16.f16.f32 "
        "{%0,%1,%2,%3}, {%4,%5,%6,%7}, {%8,%9}, {%0,%1,%2,%3};"
        : "+f"(c[0]), "+f"(c[1]), "+f"(c[2]), "+f"(c[3])
        : "r"(a[0]), "r"(a[1]), "r"(a[2]), "r"(a[3]), "r"(b[0]), "r"(b[1]));
}

// ---------------------------------------------------------------------------
// Prep kernels
// ---------------------------------------------------------------------------
__global__ __launch_bounds__(256) void prep_x(const float* __restrict__ x) {
    size_t i = ((size_t)blockIdx.x * 256 + threadIdx.x) * 4;
    float4 v = *(const float4*)(x + i);
    *(__half2*)(g_xh + i)     = __floats2half2_rn(v.x, v.y);
    *(__half2*)(g_xh + i + 2) = __floats2half2_rn(v.z, v.w);
}

__global__ __launch_bounds__(256) void prep_w(
    const float* __restrict__ Wq, const float* __restrict__ bq,
    const float* __restrict__ Wk, const float* __restrict__ bk,
    const float* __restrict__ Wv, const float* __restrict__ bv)
{
    int i = blockIdx.x * 256 + threadIdx.x;          // over NTOT*En
    int n = i >> 10;
    int e = i & 1023;
    int p = n >> 10;
    int h = (n >> 6) & 15;
    int d = n & 63;
    const float* W = (p == 0) ? Wq : ((p == 1) ? Wk : Wv);
    g_Wth[i] = __float2half_rn(W[((size_t)h * En + e) * Dn + d]);
    if (i < NTOT) {
        int pb = i >> 10;
        int hb = (i >> 6) & 15;
        int db = i & 63;
        const float* bb = (pb == 0) ? bq : ((pb == 1) ? bk : bv);
        g_bias[i] = bb[hb * Dn + db];
    }
}

__global__ __launch_bounds__(256) void prep_wo(const float* __restrict__ Wo) {
    size_t i = ((size_t)blockIdx.x * 256 + threadIdx.x) * 4;
    float4 v = *(const float4*)(Wo + i);
    *(__half2*)(g_Woh + i)     = __floats2half2_rn(v.x, v.y);
    *(__half2*)(g_Woh + i + 2) = __floats2half2_rn(v.z, v.w);
}

// ---------------------------------------------------------------------------
// fp16 warp-MMA GEMM (round-8 structure, forced 3 CTAs/SM)
// 256 threads; block 128x128; 8 warps of 64x32 (acc[4][4][4]); GBK=64.
// mode 0: Q/K -> [bh][s][d], V -> [bh][d][s]; mode 1: fp32 row-major out
// ---------------------------------------------------------------------------
__global__ __launch_bounds__(256, 3) void gemm_mma(
    const __half* __restrict__ A, const __half* __restrict__ Bmat,
    const float* __restrict__ bias,
    __half* __restrict__ qo, __half* __restrict__ ko, __half* __restrict__ vo,
    float* __restrict__ out, int mode)
{
    extern __shared__ __half sm[];
    __half* As = sm;                        // 2 x [128][72]
    __half* Bs = sm + 2 * GBM * GP;         // 2 x [128][72]

    const int tid = threadIdx.x;
    const int wid = tid >> 5;
    const int L   = tid & 31;
    const int g   = L >> 2;
    const int t   = L & 3;
    const int wm0 = (wid & 1) * 64;
    const int wn0 = (wid >> 1) * 32;

    const int m0 = blockIdx.x * GBM;
    const int n0 = blockIdx.y * GBN;

    const __half* Ag = A + (size_t)m0 * En;
    const __half* Bg = Bmat + (size_t)n0 * En;

    const uint32_t sA = smem_u32(As);
    const uint32_t sB = smem_u32(Bs);

    auto issue = [&](int kc) {
        const int buf = kc & 1;
        const int k0 = kc * GBK;
        const uint32_t ab = sA + buf * (GBM * GP * 2);
        const uint32_t bb = sB + buf * (GBN * GP * 2);
        #pragma unroll
        for (int it = 0; it < 4; it++) {     // A: 128 rows x 8 granules(8h)
            int idx = tid + it * 256;
            int r = idx >> 3, c8 = idx & 7;
            cp16(ab + (uint32_t)(r * GP + c8 * 8) * 2, Ag + (size_t)r * En + k0 + c8 * 8);
        }
        #pragma unroll
        for (int it = 0; it < 4; it++) {     // B: 128 rows x 8 granules
            int idx = tid + it * 256;
            int r = idx >> 3, c8 = idx & 7;
            cp16(bb + (uint32_t)(r * GP + c8 * 8) * 2, Bg + (size_t)r * En + k0 + c8 * 8);
        }
        CP_COMMIT();
    };

    float acc[4][4][4] = {};

    issue(0);
    for (int kc = 0; kc < NC; kc++) {
        if (kc + 1 < NC) { issue(kc + 1); CP_WAIT1(); }
        else             { CP_WAIT0(); }
        __syncthreads();

        const __half* Ab = As + (kc & 1) * (GBM * GP);
        const __half* Bb = Bs + (kc & 1) * (GBN * GP);

        #pragma unroll
        for (int ks = 0; ks < 4; ks++) {     // GBK=64 / k16
            uint32_t bfr[4][2];
            #pragma unroll
            for (int nt = 0; nt < 4; nt++) {
                const __half* bp = Bb + (wn0 + nt * 8 + g) * GP + ks * 16 + 2 * t;
                bfr[nt][0] = ldh2(bp);
                bfr[nt][1] = ldh2(bp + 8);
            }
            #pragma unroll
            for (int mt = 0; mt < 4; mt++) {
                const __half* ap = Ab + (wm0 + mt * 16 + g) * GP + ks * 16 + 2 * t;
                uint32_t af[4];
                af[0] = ldh2(ap);
                af[1] = ldh2(ap + 8 * GP);
                af[2] = ldh2(ap + 8);
                af[3] = ldh2(ap + 8 * GP + 8);
                #pragma unroll
                for (int nt = 0; nt < 4; nt++) mma16(acc[mt][nt], af, bfr[nt]);
            }
        }
        __syncthreads();
    }

    // Epilogue
    #pragma unroll
    for (int mt = 0; mt < 4; mt++) {
        const int r1 = m0 + wm0 + mt * 16 + g;
        const int r2 = r1 + 8;
        #pragma unroll
        for (int nt = 0; nt < 4; nt++) {
            const int ntile = n0 + wn0 + nt * 8;
            const int col = ntile + 2 * t;
            const float2 bb2 = *(const float2*)(bias + col);
            float v0 = acc[mt][nt][0] + bb2.x;
            float v1 = acc[mt][nt][1] + bb2.y;
            float v2 = acc[mt][nt][2] + bb2.x;
            float v3 = acc[mt][nt][3] + bb2.y;
            if (mode == 0) {
                const int proj = ntile >> 10;
                const int h    = (ntile >> 6) & 15;
                const int d    = (ntile & 63) + 2 * t;
                const int b1 = r1 >> 11, s1 = r1 & 2047;
                const int b2 = r2 >> 11, s2 = r2 & 2047;
                const int bh1 = b1 * 16 + h, bh2 = b2 * 16 + h;
                if (proj == 0) {
                    *(__half2*)(qo + ((size_t)bh1 * Sn + s1) * Dn + d) = __floats2half2_rn(v0, v1);
                    *(__half2*)(qo + ((size_t)bh2 * Sn + s2) * Dn + d) = __floats2half2_rn(v2, v3);
                } else if (proj == 1) {
                    *(__half2*)(ko + ((size_t)bh1 * Sn + s1) * Dn + d) = __floats2half2_rn(v0, v1);
                    *(__half2*)(ko + ((size_t)bh2 * Sn + s2) * Dn + d) = __floats2half2_rn(v2, v3);
                } else {
                    vo[((size_t)bh1 * Dn + d)     * Sn + s1] = __float2half_rn(v0);
                    vo[((size_t)bh1 * Dn + d + 1) * Sn + s1] = __float2half_rn(v1);
                    vo[((size_t)bh2 * Dn + d)     * Sn + s2] = __float2half_rn(v2);
                    vo[((size_t)bh2 * Dn + d + 1) * Sn + s2] = __float2half_rn(v3);
                }
            } else {
                *(float2*)(out + (size_t)r1 * En + col) = make_float2(v0, v1);
                *(float2*)(out + (size_t)r2 * En + col) = make_float2(v2, v3);
            }
        }
    }
}

// ---------------------------------------------------------------------------
// Causal flash attention (round-9 proven): fp16 MMA, 2-stage K/V double buffer.
// 128 threads; Q tile 128 = 4 warps x 32 rows (2 mt of 16); KV chunk 64.
// ---------------------------------------------------------------------------
__global__ __launch_bounds__(128) void attn_mma(__half* __restrict__ ctx)
{
    extern __shared__ __half sm[];
    __half* Qs = sm;                         // [128][72]
    __half* Ks = sm + 128 * HPAD;            // 2 x [64][72] (rows = key)
    __half* Vt = sm + 128 * HPAD + 2 * KVH;  // 2 x [64][72] (rows = d)

    const int tid = threadIdx.x;
    const int w   = tid >> 5;
    const int L   = tid & 31;
    const int g   = L >> 2;
    const int t   = L & 3;

    const int bh = blockIdx.y;
    const int b  = bh >> 4;
    const int h  = bh & 15;
    const int i0 = (gridDim.x - 1 - blockIdx.x) * 128;

    const __half* Qp = g_Qh + (size_t)bh * Sn * Dn;
    const __half* Kp = g_Kh + (size_t)bh * Sn * Dn;
    const __half* Vp = g_Vth + (size_t)bh * Dn * Sn;

    const uint32_t sQ = smem_u32(Qs);
    const uint32_t sK = smem_u32(Ks);
    const uint32_t sV = smem_u32(Vt);

    auto issueKV = [&](int ch) {
        const uint32_t off = (uint32_t)(ch & 1) * (KVH * 2);
        const int j0 = ch * 64;
        #pragma unroll
        for (int it = 0; it < 4; it++) {     // K: 64 rows x 8 granules
            int idx = tid + it * 128;
            int r = idx >> 3, c8 = idx & 7;
            cp16(sK + off + (uint32_t)(r * HPAD + c8 * 8) * 2,
                 Kp + (size_t)(j0 + r) * Dn + c8 * 8);
        }
        #pragma unroll
        for (int it = 0; it < 4; it++) {     // V^T: 64 d-rows x 8 granules
            int idx = tid + it * 128;
            int r = idx >> 3, c8 = idx & 7;
            cp16(sV + off + (uint32_t)(r * HPAD + c8 * 8) * 2,
                 Vp + (size_t)r * Sn + j0 + c8 * 8);
        }
        CP_COMMIT();
    };

    #pragma unroll
    for (int it = 0; it < 8; it++) {         // Q: 128 rows x 8 granules
        int idx = tid + it * 128;
        int r = idx >> 3, c8 = idx & 7;
        cp16(sQ + (uint32_t)(r * HPAD + c8 * 8) * 2, Qp + (size_t)(i0 + r) * Dn + c8 * 8);
    }
    issueKV(0);

    const int qr0 = i0 + w * 32;             // warp's first query row (32 rows)

    float o[2][8][4] = {};
    float mrow[2][2] = {{ -1e30f, -1e30f }, { -1e30f, -1e30f }};
    float lrow[2][2] = {{ 0.f, 0.f }, { 0.f, 0.f }};

    const int nch = i0 / 64 + 2;
    for (int ch = 0; ch < nch; ch++) {
        const int j0 = ch * 64;
        if (ch + 1 < nch) { issueKV(ch + 1); CP_WAIT1(); }
        else              { CP_WAIT0(); }
        __syncthreads();

        const __half* Kb = Ks + (ch & 1) * KVH;
        const __half* Vb = Vt + (ch & 1) * KVH;

        if (j0 <= qr0 + 31) {
            // ---- S = Q K^T ----
            float sc[2][8][4] = {};
            #pragma unroll
            for (int ks = 0; ks < 4; ks++) {
                uint32_t qa[2][4];
                #pragma unroll
                for (int mt = 0; mt < 2; mt++) {
                    const __half* qp = Qs + (w * 32 + mt * 16 + g) * HPAD + ks * 16 + 2 * t;
                    qa[mt][0] = ldh2(qp);
                    qa[mt][1] = ldh2(qp + 8 * HPAD);
                    qa[mt][2] = ldh2(qp + 8);
                    qa[mt][3] = ldh2(qp + 8 * HPAD + 8);
                }
                #pragma unroll
                for (int nt = 0; nt < 8; nt++) {
                    const __half* kp = Kb + (nt * 8 + g) * HPAD + ks * 16 + 2 * t;
                    uint32_t bb[2];
                    bb[0] = ldh2(kp);
                    bb[1] = ldh2(kp + 8);
                    mma16(sc[0][nt], qa[0], bb);
                    mma16(sc[1][nt], qa[1], bb);
                }
            }

            // ---- scale + mask + online softmax (per mt) ----
            const float scl = 0.125f;
            #pragma unroll
            for (int mt = 0; mt < 2; mt++) {
                const int r0g = qr0 + mt * 16 + g;
                const int r1g = r0g + 8;
                const bool needmask = (j0 + 63 > qr0 + mt * 16);
                #pragma unroll
                for (int nt = 0; nt < 8; nt++) {
                    const int c0 = j0 + nt * 8 + 2 * t;
                    sc[mt][nt][0] = (needmask && c0     > r0g) ? -1e30f : sc[mt][nt][0] * scl;
                    sc[mt][nt][1] = (needmask && c0 + 1 > r0g) ? -1e30f : sc[mt][nt][1] * scl;
                    sc[mt][nt][2] = (needmask && c0     > r1g) ? -1e30f : sc[mt][nt][2] * scl;
                    sc[mt][nt][3] = (needmask && c0 + 1 > r1g) ? -1e30f : sc[mt][nt][3] * scl;
                }

                float mx0 = -1e30f, mx1 = -1e30f;
                #pragma unroll
                for (int nt = 0; nt < 8; nt++) {
                    mx0 = fmaxf(mx0, fmaxf(sc[mt][nt][0], sc[mt][nt][1]));
                    mx1 = fmaxf(mx1, fmaxf(sc[mt][nt][2], sc[mt][nt][3]));
                }
                mx0 = fmaxf(mx0, __shfl_xor_sync(0xffffffffu, mx0, 1));
                mx0 = fmaxf(mx0, __shfl_xor_sync(0xffffffffu, mx0, 2));
                mx1 = fmaxf(mx1, __shfl_xor_sync(0xffffffffu, mx1, 1));
                mx1 = fmaxf(mx1, __shfl_xor_sync(0xffffffffu, mx1, 2));

                const float m0n = fmaxf(mrow[mt][0], mx0);
                const float m1n = fmaxf(mrow[mt][1], mx1);
                const float cr0 = __expf(mrow[mt][0] - m0n);
                const float cr1 = __expf(mrow[mt][1] - m1n);

                float s0 = 0.f, s1 = 0.f;
                #pragma unroll
                for (int nt = 0; nt < 8; nt++) {
                    sc[mt][nt][0] = __expf(sc[mt][nt][0] - m0n);
                    sc[mt][nt][1] = __expf(sc[mt][nt][1] - m0n);
                    sc[mt][nt][2] = __expf(sc[mt][nt][2] - m1n);
                    sc[mt][nt][3] = __expf(sc[mt][nt][3] - m1n);
                    s0 += sc[mt][nt][0] + sc[mt][nt][1];
                    s1 += sc[mt][nt][2] + sc[mt][nt][3];
                }
                s0 += __shfl_xor_sync(0xffffffffu, s0, 1);
                s0 += __shfl_xor_sync(0xffffffffu, s0, 2);
                s1 += __shfl_xor_sync(0xffffffffu, s1, 1);
                s1 += __shfl_xor_sync(0xffffffffu, s1, 2);

                lrow[mt][0] = lrow[mt][0] * cr0 + s0;  mrow[mt][0] = m0n;
                lrow[mt][1] = lrow[mt][1] * cr1 + s1;  mrow[mt][1] = m1n;

                #pragma unroll
                for (int nt = 0; nt < 8; nt++) {
                    o[mt][nt][0] *= cr0; o[mt][nt][1] *= cr0;
                    o[mt][nt][2] *= cr1; o[mt][nt][3] *= cr1;
                }
            }

            // ---- O += P V : register repack, V frags shared across mt ----
            #pragma unroll
            for (int ks = 0; ks < 4; ks++) {
                uint32_t pa[2][4];
                #pragma unroll
                for (int mt = 0; mt < 2; mt++) {
                    pa[mt][0] = packh2(sc[mt][2*ks][0],   sc[mt][2*ks][1]);
                    pa[mt][1] = packh2(sc[mt][2*ks][2],   sc[mt][2*ks][3]);
                    pa[mt][2] = packh2(sc[mt][2*ks+1][0], sc[mt][2*ks+1][1]);
                    pa[mt][3] = packh2(sc[mt][2*ks+1][2], sc[mt][2*ks+1][3]);
                }
                #pragma unroll
                for (int nt = 0; nt < 8; nt++) {
                    const __half* vp = Vb + (nt * 8 + g) * HPAD + ks * 16 + 2 * t;
                    uint32_t bb[2];
                    bb[0] = ldh2(vp);
                    bb[1] = ldh2(vp + 8);
                    mma16(o[0][nt], pa[0], bb);
                    mma16(o[1][nt], pa[1], bb);
                }
            }
        }
        __syncthreads();
    }

    // ---- epilogue ----
    #pragma unroll
    for (int mt = 0; mt < 2; mt++) {
        const float inv0 = 1.f / lrow[mt][0];
        const float inv1 = 1.f / lrow[mt][1];
        const int s0g = qr0 + mt * 16 + g;
        const int s1g = s0g + 8;
        #pragma unroll
        for (int nt = 0; nt < 8; nt++) {
            const int d = nt * 8 + 2 * t;
            *(__half2*)(ctx + ((size_t)b * Sn + s0g) * En + h * Dn + d) =
                __floats2half2_rn(o[mt][nt][0] * inv0, o[mt][nt][1] * inv0);
            *(__half2*)(ctx + ((size_t)b * Sn + s1g) * En + h * Dn + d) =
                __floats2half2_rn(o[mt][nt][2] * inv1, o[mt][nt][3] * inv1);
        }
    }
}

// ---------------------------------------------------------------------------
extern "C" void kernel_launch(void* const* d_in, const int* in_sizes, int n_in,
                              void* d_out, int out_size)
{
    const float* x  = (const float*)d_in[0];
    const float* Wq = (const float*)d_in[1];
    const float* bq = (const float*)d_in[2];
    const float* Wk = (const float*)d_in[3];
    const float* bk = (const float*)d_in[4];
    const float* Wv = (const float*)d_in[5];
    const float* bv = (const float*)d_in[6];
    const float* Wo = (const float*)d_in[7];
    const float* bo = (const float*)d_in[8];
    float* out = (float*)d_out;

    __half *qh, *kh, *vth, *ctxh, *xh, *wth, *woh;
    float *biasv;
    cudaGetSymbolAddress((void**)&qh, g_Qh);
    cudaGetSymbolAddress((void**)&kh, g_Kh);
    cudaGetSymbolAddress((void**)&vth, g_Vth);
    cudaGetSymbolAddress((void**)&ctxh, g_ctxh);
    cudaGetSymbolAddress((void**)&xh, g_xh);
    cudaGetSymbolAddress((void**)&wth, g_Wth);
    cudaGetSymbolAddress((void**)&woh, g_Woh);
    cudaGetSymbolAddress((void**)&biasv, g_bias);

    const int gemm_smem = 2 * (GBM + GBN) * GP * 2;          // 73728 B
    const int attn_smem = (128 * HPAD + 4 * 64 * HPAD) * 2;  // 55296 B
    cudaFuncSetAttribute(gemm_mma, cudaFuncAttributeMaxDynamicSharedMemorySize, gemm_smem);
    cudaFuncSetAttribute(attn_mma, cudaFuncAttributeMaxDynamicSharedMemorySize, attn_smem);

    prep_x <<<(Mn * En) / 1024, 256>>>(x);
    prep_w <<<(NTOT * En) / 256, 256>>>(Wq, bq, Wk, bk, Wv, bv);
    prep_wo<<<(En * En) / 1024, 256>>>(Wo);

    gemm_mma<<<dim3(Mn / GBM, NTOT / GBN), 256, gemm_smem>>>(
        xh, wth, biasv, qh, kh, vth, nullptr, 0);
    attn_mma<<<dim3(Sn / 128, BHn), 128, attn_smem>>>(ctxh);
    gemm_mma<<<dim3(Mn / GBM, En / GBN), 256, gemm_smem>>>(
        ctxh, woh, bo, nullptr, nullptr, nullptr, out, 1);
}

// round 13
// speedup vs baseline: 1.1702x; 1.1702x over previous
#include <cuda_runtime.h>
#include <cuda_fp16.h>
#include <cstdint>

// Problem constants
#define Bn 4
#define Sn 2048
#define En 1024
#define Hn 16
#define Dn 64
#define BHn (Bn*Hn)     // 64
#define Mn  (Bn*Sn)     // 8192
#define NTOT 3072       // 3 projections * H * D

// GEMM tile config (round-8 proven): block 128x128, 8 warps of 64x32, GBK=64
#define GBM 128
#define GBN 128
#define GBK 64
#define NC (En/GBK)     // 16 k-chunks
#define GP 72           // gemm smem row stride (halves)

// Attention: Q tile 256 rows, 8 warps x 32 rows; KV chunk 64
#define ATQ 256
#define HPAD 72
#define KVH (64 * HPAD)

// Scratch (allocation-free rule: __device__ globals)
__device__ __align__(256) __half g_Qh [(size_t)BHn * Sn * Dn];  // 16 MB
__device__ __align__(256) __half g_Kh [(size_t)BHn * Sn * Dn];  // 16 MB
__device__ __align__(256) __half g_Vth[(size_t)BHn * Dn * Sn];  // 16 MB (d-major)
__device__ __align__(256) __half g_ctxh[(size_t)Mn * En];       // 16 MB
__device__ __align__(256) __half g_xh [(size_t)Mn * En];        // 16 MB
__device__ __align__(256) __half g_Wth[(size_t)NTOT * En];      // 6 MB (K-major)
__device__ __align__(256) __half g_Woh[(size_t)En * En];        // 2 MB
__device__ __align__(256) float  g_bias[NTOT];

// ---------------------------------------------------------------------------
// Helpers
// ---------------------------------------------------------------------------
__device__ __forceinline__ uint32_t smem_u32(const void* p) {
    return (uint32_t)__cvta_generic_to_shared(p);
}
__device__ __forceinline__ void cp16(uint32_t dst, const void* src) {
    asm volatile("cp.async.cg.shared.global [%0], [%1], 16;" :: "r"(dst), "l"(src));
}
#define CP_COMMIT() asm volatile("cp.async.commit_group;" ::: "memory")
#define CP_WAIT1()  asm volatile("cp.async.wait_group 1;" ::: "memory")
#define CP_WAIT0()  asm volatile("cp.async.wait_group 0;" ::: "memory")

__device__ __forceinline__ uint32_t ldh2(const __half* p) {
    return *(const uint32_t*)p;
}
__device__ __forceinline__ uint32_t packh2(float lo, float hi) {
    __half2 h = __floats2half2_rn(lo, hi);
    return *(uint32_t*)&h;
}

// m16n8k16 fp16 MMA, fp32 accum (layout validated rounds 5-8)
__device__ __forceinline__ void mma16(float* c, const uint32_t* a, const uint32_t* b) {
    asm volatile("mma.sync.aligned.m16n8k16.row.col.f32.f16.f16.f32 "
        "{%0,%1,%2,%3}, {%4,%5,%6,%7}, {%8,%9}, {%0,%1,%2,%3};"
        : "+f"(c[0]), "+f"(c[1]), "+f"(c[2]), "+f"(c[3])
        : "r"(a[0]), "r"(a[1]), "r"(a[2]), "r"(a[3]), "r"(b[0]), "r"(b[1]));
}

// ---------------------------------------------------------------------------
// Prep kernels
// ---------------------------------------------------------------------------
__global__ __launch_bounds__(256) void prep_x(const float* __restrict__ x) {
    size_t i = ((size_t)blockIdx.x * 256 + threadIdx.x) * 4;
    float4 v = *(const float4*)(x + i);
    *(__half2*)(g_xh + i)     = __floats2half2_rn(v.x, v.y);
    *(__half2*)(g_xh + i + 2) = __floats2half2_rn(v.z, v.w);
}

__global__ __launch_bounds__(256) void prep_w(
    const float* __restrict__ Wq, const float* __restrict__ bq,
    const float* __restrict__ Wk, const float* __restrict__ bk,
    const float* __restrict__ Wv, const float* __restrict__ bv)
{
    int i = blockIdx.x * 256 + threadIdx.x;          // over NTOT*En
    int n = i >> 10;
    int e = i & 1023;
    int p = n >> 10;
    int h = (n >> 6) & 15;
    int d = n & 63;
    const float* W = (p == 0) ? Wq : ((p == 1) ? Wk : Wv);
    g_Wth[i] = __float2half_rn(W[((size_t)h * En + e) * Dn + d]);
    if (i < NTOT) {
        int pb = i >> 10;
        int hb = (i >> 6) & 15;
        int db = i & 63;
        const float* bb = (pb == 0) ? bq : ((pb == 1) ? bk : bv);
        g_bias[i] = bb[hb * Dn + db];
    }
}

__global__ __launch_bounds__(256) void prep_wo(const float* __restrict__ Wo) {
    size_t i = ((size_t)blockIdx.x * 256 + threadIdx.x) * 4;
    float4 v = *(const float4*)(Wo + i);
    *(__half2*)(g_Woh + i)     = __floats2half2_rn(v.x, v.y);
    *(__half2*)(g_Woh + i + 2) = __floats2half2_rn(v.z, v.w);
}

// ---------------------------------------------------------------------------
// fp16 warp-MMA GEMM (round-8 exact): 256 thr; 128x128; 8 warps 64x32; GBK=64
// mode 0: Q/K -> [bh][s][d], V -> [bh][d][s]; mode 1: fp32 row-major out
// ---------------------------------------------------------------------------
__global__ __launch_bounds__(256) void gemm_mma(
    const __half* __restrict__ A, const __half* __restrict__ Bmat,
    const float* __restrict__ bias,
    __half* __restrict__ qo, __half* __restrict__ ko, __half* __restrict__ vo,
    float* __restrict__ out, int mode)
{
    extern __shared__ __half sm[];
    __half* As = sm;                        // 2 x [128][72]
    __half* Bs = sm + 2 * GBM * GP;         // 2 x [128][72]

    const int tid = threadIdx.x;
    const int wid = tid >> 5;
    const int L   = tid & 31;
    const int g   = L >> 2;
    const int t   = L & 3;
    const int wm0 = (wid & 1) * 64;
    const int wn0 = (wid >> 1) * 32;

    const int m0 = blockIdx.x * GBM;
    const int n0 = blockIdx.y * GBN;

    const __half* Ag = A + (size_t)m0 * En;
    const __half* Bg = Bmat + (size_t)n0 * En;

    const uint32_t sA = smem_u32(As);
    const uint32_t sB = smem_u32(Bs);

    auto issue = [&](int kc) {
        const int buf = kc & 1;
        const int k0 = kc * GBK;
        const uint32_t ab = sA + buf * (GBM * GP * 2);
        const uint32_t bb = sB + buf * (GBN * GP * 2);
        #pragma unroll
        for (int it = 0; it < 4; it++) {     // A: 128 rows x 8 granules(8h)
            int idx = tid + it * 256;
            int r = idx >> 3, c8 = idx & 7;
            cp16(ab + (uint32_t)(r * GP + c8 * 8) * 2, Ag + (size_t)r * En + k0 + c8 * 8);
        }
        #pragma unroll
        for (int it = 0; it < 4; it++) {     // B: 128 rows x 8 granules
            int idx = tid + it * 256;
            int r = idx >> 3, c8 = idx & 7;
            cp16(bb + (uint32_t)(r * GP + c8 * 8) * 2, Bg + (size_t)r * En + k0 + c8 * 8);
        }
        CP_COMMIT();
    };

    float acc[4][4][4] = {};

    issue(0);
    for (int kc = 0; kc < NC; kc++) {
        if (kc + 1 < NC) { issue(kc + 1); CP_WAIT1(); }
        else             { CP_WAIT0(); }
        __syncthreads();

        const __half* Ab = As + (kc & 1) * (GBM * GP);
        const __half* Bb = Bs + (kc & 1) * (GBN * GP);

        #pragma unroll
        for (int ks = 0; ks < 4; ks++) {     // GBK=64 / k16
            uint32_t bfr[4][2];
            #pragma unroll
            for (int nt = 0; nt < 4; nt++) {
                const __half* bp = Bb + (wn0 + nt * 8 + g) * GP + ks * 16 + 2 * t;
                bfr[nt][0] = ldh2(bp);
                bfr[nt][1] = ldh2(bp + 8);
            }
            #pragma unroll
            for (int mt = 0; mt < 4; mt++) {
                const __half* ap = Ab + (wm0 + mt * 16 + g) * GP + ks * 16 + 2 * t;
                uint32_t af[4];
                af[0] = ldh2(ap);
                af[1] = ldh2(ap + 8 * GP);
                af[2] = ldh2(ap + 8);
                af[3] = ldh2(ap + 8 * GP + 8);
                #pragma unroll
                for (int nt = 0; nt < 4; nt++) mma16(acc[mt][nt], af, bfr[nt]);
            }
        }
        __syncthreads();
    }

    // Epilogue
    #pragma unroll
    for (int mt = 0; mt < 4; mt++) {
        const int r1 = m0 + wm0 + mt * 16 + g;
        const int r2 = r1 + 8;
        #pragma unroll
        for (int nt = 0; nt < 4; nt++) {
            const int ntile = n0 + wn0 + nt * 8;
            const int col = ntile + 2 * t;
            const float2 bb2 = *(const float2*)(bias + col);
            float v0 = acc[mt][nt][0] + bb2.x;
            float v1 = acc[mt][nt][1] + bb2.y;
            float v2 = acc[mt][nt][2] + bb2.x;
            float v3 = acc[mt][nt][3] + bb2.y;
            if (mode == 0) {
                const int proj = ntile >> 10;
                const int h    = (ntile >> 6) & 15;
                const int d    = (ntile & 63) + 2 * t;
                const int b1 = r1 >> 11, s1 = r1 & 2047;
                const int b2 = r2 >> 11, s2 = r2 & 2047;
                const int bh1 = b1 * 16 + h, bh2 = b2 * 16 + h;
                if (proj == 0) {
                    *(__half2*)(qo + ((size_t)bh1 * Sn + s1) * Dn + d) = __floats2half2_rn(v0, v1);
                    *(__half2*)(qo + ((size_t)bh2 * Sn + s2) * Dn + d) = __floats2half2_rn(v2, v3);
                } else if (proj == 1) {
                    *(__half2*)(ko + ((size_t)bh1 * Sn + s1) * Dn + d) = __floats2half2_rn(v0, v1);
                    *(__half2*)(ko + ((size_t)bh2 * Sn + s2) * Dn + d) = __floats2half2_rn(v2, v3);
                } else {
                    vo[((size_t)bh1 * Dn + d)     * Sn + s1] = __float2half_rn(v0);
                    vo[((size_t)bh1 * Dn + d + 1) * Sn + s1] = __float2half_rn(v1);
                    vo[((size_t)bh2 * Dn + d)     * Sn + s2] = __float2half_rn(v2);
                    vo[((size_t)bh2 * Dn + d + 1) * Sn + s2] = __float2half_rn(v3);
                }
            } else {
                *(float2*)(out + (size_t)r1 * En + col) = make_float2(v0, v1);
                *(float2*)(out + (size_t)r2 * En + col) = make_float2(v2, v3);
            }
        }
    }
}

// ---------------------------------------------------------------------------
// Causal flash attention: Q tile 256 (8 warps x 32 rows), 256 threads,
// 2-stage K/V double buffer, KV chunk 64. Inner warp code = round-9 validated.
// ---------------------------------------------------------------------------
__global__ __launch_bounds__(256) void attn_mma(__half* __restrict__ ctx)
{
    extern __shared__ __half sm[];
    __half* Qs = sm;                         // [256][72]
    __half* Ks = sm + ATQ * HPAD;            // 2 x [64][72] (rows = key)
    __half* Vt = sm + ATQ * HPAD + 2 * KVH;  // 2 x [64][72] (rows = d)

    const int tid = threadIdx.x;
    const int w   = tid >> 5;                // 0..7
    const int L   = tid & 31;
    const int g   = L >> 2;
    const int t   = L & 3;

    const int bh = blockIdx.y;
    const int b  = bh >> 4;
    const int h  = bh & 15;
    const int i0 = (gridDim.x - 1 - blockIdx.x) * ATQ;

    const __half* Qp = g_Qh + (size_t)bh * Sn * Dn;
    const __half* Kp = g_Kh + (size_t)bh * Sn * Dn;
    const __half* Vp = g_Vth + (size_t)bh * Dn * Sn;

    const uint32_t sQ = smem_u32(Qs);
    const uint32_t sK = smem_u32(Ks);
    const uint32_t sV = smem_u32(Vt);

    auto issueKV = [&](int ch) {
        const uint32_t off = (uint32_t)(ch & 1) * (KVH * 2);
        const int j0 = ch * 64;
        #pragma unroll
        for (int it = 0; it < 2; it++) {     // K: 64 rows x 8 granules
            int idx = tid + it * 256;
            int r = idx >> 3, c8 = idx & 7;
            cp16(sK + off + (uint32_t)(r * HPAD + c8 * 8) * 2,
                 Kp + (size_t)(j0 + r) * Dn + c8 * 8);
        }
        #pragma unroll
        for (int it = 0; it < 2; it++) {     // V^T: 64 d-rows x 8 granules
            int idx = tid + it * 256;
            int r = idx >> 3, c8 = idx & 7;
            cp16(sV + off + (uint32_t)(r * HPAD + c8 * 8) * 2,
                 Vp + (size_t)r * Sn + j0 + c8 * 8);
        }
        CP_COMMIT();
    };

    #pragma unroll
    for (int it = 0; it < 8; it++) {         // Q: 256 rows x 8 granules
        int idx = tid + it * 256;
        int r = idx >> 3, c8 = idx & 7;
        cp16(sQ + (uint32_t)(r * HPAD + c8 * 8) * 2, Qp + (size_t)(i0 + r) * Dn + c8 * 8);
    }
    issueKV(0);

    const int qr0 = i0 + w * 32;             // warp's first query row (32 rows)

    float o[2][8][4] = {};
    float mrow[2][2] = {{ -1e30f, -1e30f }, { -1e30f, -1e30f }};
    float lrow[2][2] = {{ 0.f, 0.f }, { 0.f, 0.f }};

    const int nch = i0 / 64 + 4;             // keys 0 .. i0+255
    for (int ch = 0; ch < nch; ch++) {
        const int j0 = ch * 64;
        if (ch + 1 < nch) { issueKV(ch + 1); CP_WAIT1(); }
        else              { CP_WAIT0(); }
        __syncthreads();

        const __half* Kb = Ks + (ch & 1) * KVH;
        const __half* Vb = Vt + (ch & 1) * KVH;

        if (j0 <= qr0 + 31) {
            // ---- S = Q K^T ----
            float sc[2][8][4] = {};
            #pragma unroll
            for (int ks = 0; ks < 4; ks++) {
                uint32_t qa[2][4];
                #pragma unroll
                for (int mt = 0; mt < 2; mt++) {
                    const __half* qp = Qs + (w * 32 + mt * 16 + g) * HPAD + ks * 16 + 2 * t;
                    qa[mt][0] = ldh2(qp);
                    qa[mt][1] = ldh2(qp + 8 * HPAD);
                    qa[mt][2] = ldh2(qp + 8);
                    qa[mt][3] = ldh2(qp + 8 * HPAD + 8);
                }
                #pragma unroll
                for (int nt = 0; nt < 8; nt++) {
                    const __half* kp = Kb + (nt * 8 + g) * HPAD + ks * 16 + 2 * t;
                    uint32_t bb[2];
                    bb[0] = ldh2(kp);
                    bb[1] = ldh2(kp + 8);
                    mma16(sc[0][nt], qa[0], bb);
                    mma16(sc[1][nt], qa[1], bb);
                }
            }

            // ---- scale + mask + online softmax (per mt) ----
            const float scl = 0.125f;
            #pragma unroll
            for (int mt = 0; mt < 2; mt++) {
                const int r0g = qr0 + mt * 16 + g;
                const int r1g = r0g + 8;
                const bool needmask = (j0 + 63 > qr0 + mt * 16);
                #pragma unroll
                for (int nt = 0; nt < 8; nt++) {
                    const int c0 = j0 + nt * 8 + 2 * t;
                    sc[mt][nt][0] = (needmask && c0     > r0g) ? -1e30f : sc[mt][nt][0] * scl;
                    sc[mt][nt][1] = (needmask && c0 + 1 > r0g) ? -1e30f : sc[mt][nt][1] * scl;
                    sc[mt][nt][2] = (needmask && c0     > r1g) ? -1e30f : sc[mt][nt][2] * scl;
                    sc[mt][nt][3] = (needmask && c0 + 1 > r1g) ? -1e30f : sc[mt][nt][3] * scl;
                }

                float mx0 = -1e30f, mx1 = -1e30f;
                #pragma unroll
                for (int nt = 0; nt < 8; nt++) {
                    mx0 = fmaxf(mx0, fmaxf(sc[mt][nt][0], sc[mt][nt][1]));
                    mx1 = fmaxf(mx1, fmaxf(sc[mt][nt][2], sc[mt][nt][3]));
                }
                mx0 = fmaxf(mx0, __shfl_xor_sync(0xffffffffu, mx0, 1));
                mx0 = fmaxf(mx0, __shfl_xor_sync(0xffffffffu, mx0, 2));
                mx1 = fmaxf(mx1, __shfl_xor_sync(0xffffffffu, mx1, 1));
                mx1 = fmaxf(mx1, __shfl_xor_sync(0xffffffffu, mx1, 2));

                const float m0n = fmaxf(mrow[mt][0], mx0);
                const float m1n = fmaxf(mrow[mt][1], mx1);
                const float cr0 = __expf(mrow[mt][0] - m0n);
                const float cr1 = __expf(mrow[mt][1] - m1n);

                float s0 = 0.f, s1 = 0.f;
                #pragma unroll
                for (int nt = 0; nt < 8; nt++) {
                    sc[mt][nt][0] = __expf(sc[mt][nt][0] - m0n);
                    sc[mt][nt][1] = __expf(sc[mt][nt][1] - m0n);
                    sc[mt][nt][2] = __expf(sc[mt][nt][2] - m1n);
                    sc[mt][nt][3] = __expf(sc[mt][nt][3] - m1n);
                    s0 += sc[mt][nt][0] + sc[mt][nt][1];
                    s1 += sc[mt][nt][2] + sc[mt][nt][3];
                }
                s0 += __shfl_xor_sync(0xffffffffu, s0, 1);
                s0 += __shfl_xor_sync(0xffffffffu, s0, 2);
                s1 += __shfl_xor_sync(0xffffffffu, s1, 1);
                s1 += __shfl_xor_sync(0xffffffffu, s1, 2);

                lrow[mt][0] = lrow[mt][0] * cr0 + s0;  mrow[mt][0] = m0n;
                lrow[mt][1] = lrow[mt][1] * cr1 + s1;  mrow[mt][1] = m1n;

                #pragma unroll
                for (int nt = 0; nt < 8; nt++) {
                    o[mt][nt][0] *= cr0; o[mt][nt][1] *= cr0;
                    o[mt][nt][2] *= cr1; o[mt][nt][3] *= cr1;
                }
            }

            // ---- O += P V : register repack, V frags shared across mt ----
            #pragma unroll
            for (int ks = 0; ks < 4; ks++) {
                uint32_t pa[2][4];
                #pragma unroll
                for (int mt = 0; mt < 2; mt++) {
                    pa[mt][0] = packh2(sc[mt][2*ks][0],   sc[mt][2*ks][1]);
                    pa[mt][1] = packh2(sc[mt][2*ks][2],   sc[mt][2*ks][3]);
                    pa[mt][2] = packh2(sc[mt][2*ks+1][0], sc[mt][2*ks+1][1]);
                    pa[mt][3] = packh2(sc[mt][2*ks+1][2], sc[mt][2*ks+1][3]);
                }
                #pragma unroll
                for (int nt = 0; nt < 8; nt++) {
                    const __half* vp = Vb + (nt * 8 + g) * HPAD + ks * 16 + 2 * t;
                    uint32_t bb[2];
                    bb[0] = ldh2(vp);
                    bb[1] = ldh2(vp + 8);
                    mma16(o[0][nt], pa[0], bb);
                    mma16(o[1][nt], pa[1], bb);
                }
            }
        }
        __syncthreads();
    }

    // ---- epilogue ----
    #pragma unroll
    for (int mt = 0; mt < 2; mt++) {
        const float inv0 = 1.f / lrow[mt][0];
        const float inv1 = 1.f / lrow[mt][1];
        const int s0g = qr0 + mt * 16 + g;
        const int s1g = s0g + 8;
        #pragma unroll
        for (int nt = 0; nt < 8; nt++) {
            const int d = nt * 8 + 2 * t;
            *(__half2*)(ctx + ((size_t)b * Sn + s0g) * En + h * Dn + d) =
                __floats2half2_rn(o[mt][nt][0] * inv0, o[mt][nt][1] * inv0);
            *(__half2*)(ctx + ((size_t)b * Sn + s1g) * En + h * Dn + d) =
                __floats2half2_rn(o[mt][nt][2] * inv1, o[mt][nt][3] * inv1);
        }
    }
}

// ---------------------------------------------------------------------------
extern "C" void kernel_launch(void* const* d_in, const int* in_sizes, int n_in,
                              void* d_out, int out_size)
{
    const float* x  = (const float*)d_in[0];
    const float* Wq = (const float*)d_in[1];
    const float* bq = (const float*)d_in[2];
    const float* Wk = (const float*)d_in[3];
    const float* bk = (const float*)d_in[4];
    const float* Wv = (const float*)d_in[5];
    const float* bv = (const float*)d_in[6];
    const float* Wo = (const float*)d_in[7];
    const float* bo = (const float*)d_in[8];
    float* out = (float*)d_out;

    __half *qh, *kh, *vth, *ctxh, *xh, *wth, *woh;
    float *biasv;
    cudaGetSymbolAddress((void**)&qh, g_Qh);
    cudaGetSymbolAddress((void**)&kh, g_Kh);
    cudaGetSymbolAddress((void**)&vth, g_Vth);
    cudaGetSymbolAddress((void**)&ctxh, g_ctxh);
    cudaGetSymbolAddress((void**)&xh, g_xh);
    cudaGetSymbolAddress((void**)&wth, g_Wth);
    cudaGetSymbolAddress((void**)&woh, g_Woh);
    cudaGetSymbolAddress((void**)&biasv, g_bias);

    const int gemm_smem = 2 * (GBM + GBN) * GP * 2;          // 73728 B
    const int attn_smem = (ATQ * HPAD + 4 * 64 * HPAD) * 2;  // 73728 B
    cudaFuncSetAttribute(gemm_mma, cudaFuncAttributeMaxDynamicSharedMemorySize, gemm_smem);
    cudaFuncSetAttribute(attn_mma, cudaFuncAttributeMaxDynamicSharedMemorySize, attn_smem);

    prep_x <<<(Mn * En) / 1024, 256>>>(x);
    prep_w <<<(NTOT * En) / 256, 256>>>(Wq, bq, Wk, bk, Wv, bv);
    prep_wo<<<(En * En) / 1024, 256>>>(Wo);

    gemm_mma<<<dim3(Mn / GBM, NTOT / GBN), 256, gemm_smem>>>(
        xh, wth, biasv, qh, kh, vth, nullptr, 0);
    attn_mma<<<dim3(Sn / ATQ, BHn), 256, attn_smem>>>(ctxh);
    gemm_mma<<<dim3(Mn / GBM, En / GBN), 256, gemm_smem>>>(
        ctxh, woh, bo, nullptr, nullptr, nullptr, out, 1);
}

// round 14
// speedup vs baseline: 1.2865x; 1.0993x over previous
#include <cuda_runtime.h>
#include <cuda_fp16.h>
#include <cstdint>

// Problem constants
#define Bn 4
#define Sn 2048
#define En 1024
#define Hn 16
#define Dn 64
#define BHn (Bn*Hn)     // 64
#define Mn  (Bn*Sn)     // 8192
#define NTOT 3072       // 3 projections * H * D

// GEMM tile config (round-8 proven): block 128x128, 8 warps of 64x32, GBK=64
#define GBM 128
#define GBN 128
#define GBK 64
#define NC (En/GBK)     // 16 k-chunks
#define GP 72           // gemm smem row stride (halves)

// Attention (round-9 proven shape): Q tile 128, 4 warps x 32 rows; KV chunk 64
#define HPAD 72
#define KVH (64 * HPAD)

// Q pre-scale: (1/sqrt(64)) * log2(e), folded into Q at QKV epilogue
#define QSCALE 0.1803368801111204f

// Scratch (allocation-free rule: __device__ globals)
__device__ __align__(256) __half g_Qh [(size_t)BHn * Sn * Dn];  // 16 MB
__device__ __align__(256) __half g_Kh [(size_t)BHn * Sn * Dn];  // 16 MB
__device__ __align__(256) __half g_Vth[(size_t)BHn * Dn * Sn];  // 16 MB (d-major)
__device__ __align__(256) __half g_ctxh[(size_t)Mn * En];       // 16 MB
__device__ __align__(256) __half g_xh [(size_t)Mn * En];        // 16 MB
__device__ __align__(256) __half g_Wth[(size_t)NTOT * En];      // 6 MB (K-major)
__device__ __align__(256) __half g_Woh[(size_t)En * En];        // 2 MB
__device__ __align__(256) float  g_bias[NTOT];

// ---------------------------------------------------------------------------
// Helpers
// ---------------------------------------------------------------------------
__device__ __forceinline__ uint32_t smem_u32(const void* p) {
    return (uint32_t)__cvta_generic_to_shared(p);
}
__device__ __forceinline__ void cp16(uint32_t dst, const void* src) {
    asm volatile("cp.async.cg.shared.global [%0], [%1], 16;" :: "r"(dst), "l"(src));
}
#define CP_COMMIT() asm volatile("cp.async.commit_group;" ::: "memory")
#define CP_WAIT1()  asm volatile("cp.async.wait_group 1;" ::: "memory")
#define CP_WAIT0()  asm volatile("cp.async.wait_group 0;" ::: "memory")

__device__ __forceinline__ uint32_t ldh2(const __half* p) {
    return *(const uint32_t*)p;
}
__device__ __forceinline__ uint32_t packh2(float lo, float hi) {
    __half2 h = __floats2half2_rn(lo, hi);
    return *(uint32_t*)&h;
}

// m16n8k16 fp16 MMA, fp32 accum (layout validated rounds 5-8)
__device__ __forceinline__ void mma16(float* c, const uint32_t* a, const uint32_t* b) {
    asm volatile("mma.sync.aligned.m16n8k16.row.col.f32.f16.f16.f32 "
        "{%0,%1,%2,%3}, {%4,%5,%6,%7}, {%8,%9}, {%0,%1,%2,%3};"
        : "+f"(c[0]), "+f"(c[1]), "+f"(c[2]), "+f"(c[3])
        : "r"(a[0]), "r"(a[1]), "r"(a[2]), "r"(a[3]), "r"(b[0]), "r"(b[1]));
}

// ---------------------------------------------------------------------------
// Prep kernels
// ---------------------------------------------------------------------------
__global__ __launch_bounds__(256) void prep_x(const float* __restrict__ x) {
    size_t i = ((size_t)blockIdx.x * 256 + threadIdx.x) * 4;
    float4 v = *(const float4*)(x + i);
    *(__half2*)(g_xh + i)     = __floats2half2_rn(v.x, v.y);
    *(__half2*)(g_xh + i + 2) = __floats2half2_rn(v.z, v.w);
}

__global__ __launch_bounds__(256) void prep_w(
    const float* __restrict__ Wq, const float* __restrict__ bq,
    const float* __restrict__ Wk, const float* __restrict__ bk,
    const float* __restrict__ Wv, const float* __restrict__ bv)
{
    int i = blockIdx.x * 256 + threadIdx.x;          // over NTOT*En
    int n = i >> 10;
    int e = i & 1023;
    int p = n >> 10;
    int h = (n >> 6) & 15;
    int d = n & 63;
    const float* W = (p == 0) ? Wq : ((p == 1) ? Wk : Wv);
    g_Wth[i] = __float2half_rn(W[((size_t)h * En + e) * Dn + d]);
    if (i < NTOT) {
        int pb = i >> 10;
        int hb = (i >> 6) & 15;
        int db = i & 63;
        const float* bb = (pb == 0) ? bq : ((pb == 1) ? bk : bv);
        g_bias[i] = bb[hb * Dn + db];
    }
}

__global__ __launch_bounds__(256) void prep_wo(const float* __restrict__ Wo) {
    size_t i = ((size_t)blockIdx.x * 256 + threadIdx.x) * 4;
    float4 v = *(const float4*)(Wo + i);
    *(__half2*)(g_Woh + i)     = __floats2half2_rn(v.x, v.y);
    *(__half2*)(g_Woh + i + 2) = __floats2half2_rn(v.z, v.w);
}

// ---------------------------------------------------------------------------
// fp16 warp-MMA GEMM (round-8 exact): 256 thr; 128x128; 8 warps 64x32; GBK=64
// mode 0: Q (pre-scaled by QSCALE) / K -> [bh][s][d], V -> [bh][d][s];
// mode 1: fp32 row-major out
// ---------------------------------------------------------------------------
__global__ __launch_bounds__(256) void gemm_mma(
    const __half* __restrict__ A, const __half* __restrict__ Bmat,
    const float* __restrict__ bias,
    __half* __restrict__ qo, __half* __restrict__ ko, __half* __restrict__ vo,
    float* __restrict__ out, int mode)
{
    extern __shared__ __half sm[];
    __half* As = sm;                        // 2 x [128][72]
    __half* Bs = sm + 2 * GBM * GP;         // 2 x [128][72]

    const int tid = threadIdx.x;
    const int wid = tid >> 5;
    const int L   = tid & 31;
    const int g   = L >> 2;
    const int t   = L & 3;
    const int wm0 = (wid & 1) * 64;
    const int wn0 = (wid >> 1) * 32;

    const int m0 = blockIdx.x * GBM;
    const int n0 = blockIdx.y * GBN;

    const __half* Ag = A + (size_t)m0 * En;
    const __half* Bg = Bmat + (size_t)n0 * En;

    const uint32_t sA = smem_u32(As);
    const uint32_t sB = smem_u32(Bs);

    auto issue = [&](int kc) {
        const int buf = kc & 1;
        const int k0 = kc * GBK;
        const uint32_t ab = sA + buf * (GBM * GP * 2);
        const uint32_t bb = sB + buf * (GBN * GP * 2);
        #pragma unroll
        for (int it = 0; it < 4; it++) {     // A: 128 rows x 8 granules(8h)
            int idx = tid + it * 256;
            int r = idx >> 3, c8 = idx & 7;
            cp16(ab + (uint32_t)(r * GP + c8 * 8) * 2, Ag + (size_t)r * En + k0 + c8 * 8);
        }
        #pragma unroll
        for (int it = 0; it < 4; it++) {     // B: 128 rows x 8 granules
            int idx = tid + it * 256;
            int r = idx >> 3, c8 = idx & 7;
            cp16(bb + (uint32_t)(r * GP + c8 * 8) * 2, Bg + (size_t)r * En + k0 + c8 * 8);
        }
        CP_COMMIT();
    };

    float acc[4][4][4] = {};

    issue(0);
    for (int kc = 0; kc < NC; kc++) {
        if (kc + 1 < NC) { issue(kc + 1); CP_WAIT1(); }
        else             { CP_WAIT0(); }
        __syncthreads();

        const __half* Ab = As + (kc & 1) * (GBM * GP);
        const __half* Bb = Bs + (kc & 1) * (GBN * GP);

        #pragma unroll
        for (int ks = 0; ks < 4; ks++) {     // GBK=64 / k16
            uint32_t bfr[4][2];
            #pragma unroll
            for (int nt = 0; nt < 4; nt++) {
                const __half* bp = Bb + (wn0 + nt * 8 + g) * GP + ks * 16 + 2 * t;
                bfr[nt][0] = ldh2(bp);
                bfr[nt][1] = ldh2(bp + 8);
            }
            #pragma unroll
            for (int mt = 0; mt < 4; mt++) {
                const __half* ap = Ab + (wm0 + mt * 16 + g) * GP + ks * 16 + 2 * t;
                uint32_t af[4];
                af[0] = ldh2(ap);
                af[1] = ldh2(ap + 8 * GP);
                af[2] = ldh2(ap + 8);
                af[3] = ldh2(ap + 8 * GP + 8);
                #pragma unroll
                for (int nt = 0; nt < 4; nt++) mma16(acc[mt][nt], af, bfr[nt]);
            }
        }
        __syncthreads();
    }

    // Epilogue
    #pragma unroll
    for (int mt = 0; mt < 4; mt++) {
        const int r1 = m0 + wm0 + mt * 16 + g;
        const int r2 = r1 + 8;
        #pragma unroll
        for (int nt = 0; nt < 4; nt++) {
            const int ntile = n0 + wn0 + nt * 8;
            const int col = ntile + 2 * t;
            const float2 bb2 = *(const float2*)(bias + col);
            float v0 = acc[mt][nt][0] + bb2.x;
            float v1 = acc[mt][nt][1] + bb2.y;
            float v2 = acc[mt][nt][2] + bb2.x;
            float v3 = acc[mt][nt][3] + bb2.y;
            if (mode == 0) {
                const int proj = ntile >> 10;
                const int h    = (ntile >> 6) & 15;
                const int d    = (ntile & 63) + 2 * t;
                const int b1 = r1 >> 11, s1 = r1 & 2047;
                const int b2 = r2 >> 11, s2 = r2 & 2047;
                const int bh1 = b1 * 16 + h, bh2 = b2 * 16 + h;
                if (proj == 0) {
                    // pre-scale Q by QSCALE = (1/sqrt(D)) * log2(e)
                    *(__half2*)(qo + ((size_t)bh1 * Sn + s1) * Dn + d) =
                        __floats2half2_rn(v0 * QSCALE, v1 * QSCALE);
                    *(__half2*)(qo + ((size_t)bh2 * Sn + s2) * Dn + d) =
                        __floats2half2_rn(v2 * QSCALE, v3 * QSCALE);
                } else if (proj == 1) {
                    *(__half2*)(ko + ((size_t)bh1 * Sn + s1) * Dn + d) = __floats2half2_rn(v0, v1);
                    *(__half2*)(ko + ((size_t)bh2 * Sn + s2) * Dn + d) = __floats2half2_rn(v2, v3);
                } else {
                    vo[((size_t)bh1 * Dn + d)     * Sn + s1] = __float2half_rn(v0);
                    vo[((size_t)bh1 * Dn + d + 1) * Sn + s1] = __float2half_rn(v1);
                    vo[((size_t)bh2 * Dn + d)     * Sn + s2] = __float2half_rn(v2);
                    vo[((size_t)bh2 * Dn + d + 1) * Sn + s2] = __float2half_rn(v3);
                }
            } else {
                *(float2*)(out + (size_t)r1 * En + col) = make_float2(v0, v1);
                *(float2*)(out + (size_t)r2 * En + col) = make_float2(v2, v3);
            }
        }
    }
}

// ---------------------------------------------------------------------------
// Causal flash attention (round-9 shape): fp16 MMA, 2-stage K/V double buffer.
// 128 threads; Q tile 128 = 4 warps x 32 rows (2 mt of 16); KV chunk 64.
// exp2-domain softmax (Q pre-scaled); lane-partial row sums.
// ---------------------------------------------------------------------------
__global__ __launch_bounds__(128) void attn_mma(__half* __restrict__ ctx)
{
    extern __shared__ __half sm[];
    __half* Qs = sm;                         // [128][72]
    __half* Ks = sm + 128 * HPAD;            // 2 x [64][72] (rows = key)
    __half* Vt = sm + 128 * HPAD + 2 * KVH;  // 2 x [64][72] (rows = d)

    const int tid = threadIdx.x;
    const int w   = tid >> 5;
    const int L   = tid & 31;
    const int g   = L >> 2;
    const int t   = L & 3;

    const int bh = blockIdx.y;
    const int b  = bh >> 4;
    const int h  = bh & 15;
    const int i0 = (gridDim.x - 1 - blockIdx.x) * 128;

    const __half* Qp = g_Qh + (size_t)bh * Sn * Dn;
    const __half* Kp = g_Kh + (size_t)bh * Sn * Dn;
    const __half* Vp = g_Vth + (size_t)bh * Dn * Sn;

    const uint32_t sQ = smem_u32(Qs);
    const uint32_t sK = smem_u32(Ks);
    const uint32_t sV = smem_u32(Vt);

    auto issueKV = [&](int ch) {
        const uint32_t off = (uint32_t)(ch & 1) * (KVH * 2);
        const int j0 = ch * 64;
        #pragma unroll
        for (int it = 0; it < 4; it++) {     // K: 64 rows x 8 granules
            int idx = tid + it * 128;
            int r = idx >> 3, c8 = idx & 7;
            cp16(sK + off + (uint32_t)(r * HPAD + c8 * 8) * 2,
                 Kp + (size_t)(j0 + r) * Dn + c8 * 8);
        }
        #pragma unroll
        for (int it = 0; it < 4; it++) {     // V^T: 64 d-rows x 8 granules
            int idx = tid + it * 128;
            int r = idx >> 3, c8 = idx & 7;
            cp16(sV + off + (uint32_t)(r * HPAD + c8 * 8) * 2,
                 Vp + (size_t)r * Sn + j0 + c8 * 8);
        }
        CP_COMMIT();
    };

    #pragma unroll
    for (int it = 0; it < 8; it++) {         // Q: 128 rows x 8 granules
        int idx = tid + it * 128;
        int r = idx >> 3, c8 = idx & 7;
        cp16(sQ + (uint32_t)(r * HPAD + c8 * 8) * 2, Qp + (size_t)(i0 + r) * Dn + c8 * 8);
    }
    issueKV(0);

    const int qr0 = i0 + w * 32;             // warp's first query row (32 rows)

    float o[2][8][4] = {};
    float mrow[2][2] = {{ -1e30f, -1e30f }, { -1e30f, -1e30f }};
    float lrow[2][2] = {{ 0.f, 0.f }, { 0.f, 0.f }};  // lane-partial sums

    const int nch = i0 / 64 + 2;
    for (int ch = 0; ch < nch; ch++) {
        const int j0 = ch * 64;
        if (ch + 1 < nch) { issueKV(ch + 1); CP_WAIT1(); }
        else              { CP_WAIT0(); }
        __syncthreads();

        const __half* Kb = Ks + (ch & 1) * KVH;
        const __half* Vb = Vt + (ch & 1) * KVH;

        if (j0 <= qr0 + 31) {
            // ---- S = Q K^T (already in log2 domain via Q pre-scale) ----
            float sc[2][8][4] = {};
            #pragma unroll
            for (int ks = 0; ks < 4; ks++) {
                uint32_t qa[2][4];
                #pragma unroll
                for (int mt = 0; mt < 2; mt++) {
                    const __half* qp = Qs + (w * 32 + mt * 16 + g) * HPAD + ks * 16 + 2 * t;
                    qa[mt][0] = ldh2(qp);
                    qa[mt][1] = ldh2(qp + 8 * HPAD);
                    qa[mt][2] = ldh2(qp + 8);
                    qa[mt][3] = ldh2(qp + 8 * HPAD + 8);
                }
                #pragma unroll
                for (int nt = 0; nt < 8; nt++) {
                    const __half* kp = Kb + (nt * 8 + g) * HPAD + ks * 16 + 2 * t;
                    uint32_t bb[2];
                    bb[0] = ldh2(kp);
                    bb[1] = ldh2(kp + 8);
                    mma16(sc[0][nt], qa[0], bb);
                    mma16(sc[1][nt], qa[1], bb);
                }
            }

            // ---- causal mask + online softmax (exp2 domain, per mt) ----
            #pragma unroll
            for (int mt = 0; mt < 2; mt++) {
                const int r0g = qr0 + mt * 16 + g;
                const int r1g = r0g + 8;
                const bool needmask = (j0 + 63 > qr0 + mt * 16);
                if (needmask) {
                    #pragma unroll
                    for (int nt = 0; nt < 8; nt++) {
                        const int c0 = j0 + nt * 8 + 2 * t;
                        if (c0     > r0g) sc[mt][nt][0] = -1e30f;
                        if (c0 + 1 > r0g) sc[mt][nt][1] = -1e30f;
                        if (c0     > r1g) sc[mt][nt][2] = -1e30f;
                        if (c0 + 1 > r1g) sc[mt][nt][3] = -1e30f;
                    }
                }

                float mx0 = -1e30f, mx1 = -1e30f;
                #pragma unroll
                for (int nt = 0; nt < 8; nt++) {
                    mx0 = fmaxf(mx0, fmaxf(sc[mt][nt][0], sc[mt][nt][1]));
                    mx1 = fmaxf(mx1, fmaxf(sc[mt][nt][2], sc[mt][nt][3]));
                }
                mx0 = fmaxf(mx0, __shfl_xor_sync(0xffffffffu, mx0, 1));
                mx0 = fmaxf(mx0, __shfl_xor_sync(0xffffffffu, mx0, 2));
                mx1 = fmaxf(mx1, __shfl_xor_sync(0xffffffffu, mx1, 1));
                mx1 = fmaxf(mx1, __shfl_xor_sync(0xffffffffu, mx1, 2));

                const float m0n = fmaxf(mrow[mt][0], mx0);
                const float m1n = fmaxf(mrow[mt][1], mx1);
                const float cr0 = exp2f(mrow[mt][0] - m0n);
                const float cr1 = exp2f(mrow[mt][1] - m1n);

                float s0 = 0.f, s1 = 0.f;
                #pragma unroll
                for (int nt = 0; nt < 8; nt++) {
                    sc[mt][nt][0] = exp2f(sc[mt][nt][0] - m0n);
                    sc[mt][nt][1] = exp2f(sc[mt][nt][1] - m0n);
                    sc[mt][nt][2] = exp2f(sc[mt][nt][2] - m1n);
                    sc[mt][nt][3] = exp2f(sc[mt][nt][3] - m1n);
                    s0 += sc[mt][nt][0] + sc[mt][nt][1];
                    s1 += sc[mt][nt][2] + sc[mt][nt][3];
                }
                // lane-partial accumulation (cross-lane reduce deferred)
                lrow[mt][0] = lrow[mt][0] * cr0 + s0;  mrow[mt][0] = m0n;
                lrow[mt][1] = lrow[mt][1] * cr1 + s1;  mrow[mt][1] = m1n;

                #pragma unroll
                for (int nt = 0; nt < 8; nt++) {
                    o[mt][nt][0] *= cr0; o[mt][nt][1] *= cr0;
                    o[mt][nt][2] *= cr1; o[mt][nt][3] *= cr1;
                }
            }

            // ---- O += P V : register repack, V frags shared across mt ----
            #pragma unroll
            for (int ks = 0; ks < 4; ks++) {
                uint32_t pa[2][4];
                #pragma unroll
                for (int mt = 0; mt < 2; mt++) {
                    pa[mt][0] = packh2(sc[mt][2*ks][0],   sc[mt][2*ks][1]);
                    pa[mt][1] = packh2(sc[mt][2*ks][2],   sc[mt][2*ks][3]);
                    pa[mt][2] = packh2(sc[mt][2*ks+1][0], sc[mt][2*ks+1][1]);
                    pa[mt][3] = packh2(sc[mt][2*ks+1][2], sc[mt][2*ks+1][3]);
                }
                #pragma unroll
                for (int nt = 0; nt < 8; nt++) {
                    const __half* vp = Vb + (nt * 8 + g) * HPAD + ks * 16 + 2 * t;
                    uint32_t bb[2];
                    bb[0] = ldh2(vp);
                    bb[1] = ldh2(vp + 8);
                    mma16(o[0][nt], pa[0], bb);
                    mma16(o[1][nt], pa[1], bb);
                }
            }
        }
        __syncthreads();
    }

    // ---- epilogue: reduce lane-partial sums, normalize, write ctx ----
    #pragma unroll
    for (int mt = 0; mt < 2; mt++) {
        float s0 = lrow[mt][0], s1 = lrow[mt][1];
        s0 += __shfl_xor_sync(0xffffffffu, s0, 1);
        s0 += __shfl_xor_sync(0xffffffffu, s0, 2);
        s1 += __shfl_xor_sync(0xffffffffu, s1, 1);
        s1 += __shfl_xor_sync(0xffffffffu, s1, 2);
        const float inv0 = 1.f / s0;
        const float inv1 = 1.f / s1;
        const int s0g = qr0 + mt * 16 + g;
        const int s1g = s0g + 8;
        #pragma unroll
        for (int nt = 0; nt < 8; nt++) {
            const int d = nt * 8 + 2 * t;
            *(__half2*)(ctx + ((size_t)b * Sn + s0g) * En + h * Dn + d) =
                __floats2half2_rn(o[mt][nt][0] * inv0, o[mt][nt][1] * inv0);
            *(__half2*)(ctx + ((size_t)b * Sn + s1g) * En + h * Dn + d) =
                __floats2half2_rn(o[mt][nt][2] * inv1, o[mt][nt][3] * inv1);
        }
    }
}

// ---------------------------------------------------------------------------
extern "C" void kernel_launch(void* const* d_in, const int* in_sizes, int n_in,
                              void* d_out, int out_size)
{
    const float* x  = (const float*)d_in[0];
    const float* Wq = (const float*)d_in[1];
    const float* bq = (const float*)d_in[2];
    const float* Wk = (const float*)d_in[3];
    const float* bk = (const float*)d_in[4];
    const float* Wv = (const float*)d_in[5];
    const float* bv = (const float*)d_in[6];
    const float* Wo = (const float*)d_in[7];
    const float* bo = (const float*)d_in[8];
    float* out = (float*)d_out;

    __half *qh, *kh, *vth, *ctxh, *xh, *wth, *woh;
    float *biasv;
    cudaGetSymbolAddress((void**)&qh, g_Qh);
    cudaGetSymbolAddress((void**)&kh, g_Kh);
    cudaGetSymbolAddress((void**)&vth, g_Vth);
    cudaGetSymbolAddress((void**)&ctxh, g_ctxh);
    cudaGetSymbolAddress((void**)&xh, g_xh);
    cudaGetSymbolAddress((void**)&wth, g_Wth);
    cudaGetSymbolAddress((void**)&woh, g_Woh);
    cudaGetSymbolAddress((void**)&biasv, g_bias);

    const int gemm_smem = 2 * (GBM + GBN) * GP * 2;          // 73728 B
    const int attn_smem = (128 * HPAD + 4 * 64 * HPAD) * 2;  // 55296 B
    cudaFuncSetAttribute(gemm_mma, cudaFuncAttributeMaxDynamicSharedMemorySize, gemm_smem);
    cudaFuncSetAttribute(attn_mma, cudaFuncAttributeMaxDynamicSharedMemorySize, attn_smem);

    prep_x <<<(Mn * En) / 1024, 256>>>(x);
    prep_w <<<(NTOT * En) / 256, 256>>>(Wq, bq, Wk, bk, Wv, bv);
    prep_wo<<<(En * En) / 1024, 256>>>(Wo);

    gemm_mma<<<dim3(Mn / GBM, NTOT / GBN), 256, gemm_smem>>>(
        xh, wth, biasv, qh, kh, vth, nullptr, 0);
    attn_mma<<<dim3(Sn / 128, BHn), 128, attn_smem>>>(ctxh);
    gemm_mma<<<dim3(Mn / GBM, En / GBN), 256, gemm_smem>>>(
        ctxh, woh, bo, nullptr, nullptr, nullptr, out, 1);
}

// round 15
// speedup vs baseline: 1.2918x; 1.0042x over previous
#include <cuda_runtime.h>
#include <cuda_fp16.h>
#include <cstdint>

// Problem constants
#define Bn 4
#define Sn 2048
#define En 1024
#define Hn 16
#define Dn 64
#define BHn (Bn*Hn)     // 64
#define Mn  (Bn*Sn)     // 8192
#define NTOT 3072       // 3 projections * H * D

// GEMM tile config (round-8 proven): block 128x128, 8 warps of 64x32, GBK=64
#define GBM 128
#define GBN 128
#define GBK 64
#define NC (En/GBK)     // 16 k-chunks
#define GP 72           // gemm smem row stride (halves)

// Attention (round-9 proven shape): Q tile 128, 4 warps x 32 rows; KV chunk 64
#define HPAD 72
#define KVH (64 * HPAD)

// Q pre-scale: (1/sqrt(64)) * log2(e), folded into Q at QKV epilogue
#define QSCALE 0.1803368801111204f
// packed half2 {1.0, 1.0}
#define ONES_H2 0x3C003C00u

// Scratch (allocation-free rule: __device__ globals)
__device__ __align__(256) __half g_Qh [(size_t)BHn * Sn * Dn];  // 16 MB
__device__ __align__(256) __half g_Kh [(size_t)BHn * Sn * Dn];  // 16 MB
__device__ __align__(256) __half g_Vth[(size_t)BHn * Dn * Sn];  // 16 MB (d-major)
__device__ __align__(256) __half g_ctxh[(size_t)Mn * En];       // 16 MB
__device__ __align__(256) __half g_xh [(size_t)Mn * En];        // 16 MB
__device__ __align__(256) __half g_Wth[(size_t)NTOT * En];      // 6 MB (K-major)
__device__ __align__(256) __half g_Woh[(size_t)En * En];        // 2 MB
__device__ __align__(256) float  g_bias[NTOT];

// ---------------------------------------------------------------------------
// Helpers
// ---------------------------------------------------------------------------
__device__ __forceinline__ uint32_t smem_u32(const void* p) {
    return (uint32_t)__cvta_generic_to_shared(p);
}
__device__ __forceinline__ void cp16(uint32_t dst, const void* src) {
    asm volatile("cp.async.cg.shared.global [%0], [%1], 16;" :: "r"(dst), "l"(src));
}
#define CP_COMMIT() asm volatile("cp.async.commit_group;" ::: "memory")
#define CP_WAIT1()  asm volatile("cp.async.wait_group 1;" ::: "memory")
#define CP_WAIT0()  asm volatile("cp.async.wait_group 0;" ::: "memory")

__device__ __forceinline__ uint32_t ldh2(const __half* p) {
    return *(const uint32_t*)p;
}
__device__ __forceinline__ uint32_t packh2(float lo, float hi) {
    __half2 h = __floats2half2_rn(lo, hi);
    return *(uint32_t*)&h;
}
// pack (lo,hi) to half2, then exp2 both halves in one MUFU op
__device__ __forceinline__ uint32_t ex2h2(float lo, float hi) {
    uint32_t p = packh2(lo, hi);
    uint32_t r;
    asm("ex2.approx.f16x2 %0, %1;" : "=r"(r) : "r"(p));
    return r;
}

// m16n8k16 fp16 MMA, fp32 accum (layout validated rounds 5-8)
__device__ __forceinline__ void mma16(float* c, const uint32_t* a, const uint32_t* b) {
    asm volatile("mma.sync.aligned.m16n8k16.row.col.f32.f16.f16.f32 "
        "{%0,%1,%2,%3}, {%4,%5,%6,%7}, {%8,%9}, {%0,%1,%2,%3};"
        : "+f"(c[0]), "+f"(c[1]), "+f"(c[2]), "+f"(c[3])
        : "r"(a[0]), "r"(a[1]), "r"(a[2]), "r"(a[3]), "r"(b[0]), "r"(b[1]));
}

// ---------------------------------------------------------------------------
// Prep kernels
// ---------------------------------------------------------------------------
__global__ __launch_bounds__(256) void prep_x(const float* __restrict__ x) {
    size_t i = ((size_t)blockIdx.x * 256 + threadIdx.x) * 4;
    float4 v = *(const float4*)(x + i);
    *(__half2*)(g_xh + i)     = __floats2half2_rn(v.x, v.y);
    *(__half2*)(g_xh + i + 2) = __floats2half2_rn(v.z, v.w);
}

__global__ __launch_bounds__(256) void prep_w(
    const float* __restrict__ Wq, const float* __restrict__ bq,
    const float* __restrict__ Wk, const float* __restrict__ bk,
    const float* __restrict__ Wv, const float* __restrict__ bv)
{
    int i = blockIdx.x * 256 + threadIdx.x;          // over NTOT*En
    int n = i >> 10;
    int e = i & 1023;
    int p = n >> 10;
    int h = (n >> 6) & 15;
    int d = n & 63;
    const float* W = (p == 0) ? Wq : ((p == 1) ? Wk : Wv);
    g_Wth[i] = __float2half_rn(W[((size_t)h * En + e) * Dn + d]);
    if (i < NTOT) {
        int pb = i >> 10;
        int hb = (i >> 6) & 15;
        int db = i & 63;
        const float* bb = (pb == 0) ? bq : ((pb == 1) ? bk : bv);
        g_bias[i] = bb[hb * Dn + db];
    }
}

__global__ __launch_bounds__(256) void prep_wo(const float* __restrict__ Wo) {
    size_t i = ((size_t)blockIdx.x * 256 + threadIdx.x) * 4;
    float4 v = *(const float4*)(Wo + i);
    *(__half2*)(g_Woh + i)     = __floats2half2_rn(v.x, v.y);
    *(__half2*)(g_Woh + i + 2) = __floats2half2_rn(v.z, v.w);
}

// ---------------------------------------------------------------------------
// fp16 warp-MMA GEMM (round-8 exact): 256 thr; 128x128; 8 warps 64x32; GBK=64
// mode 0: Q (pre-scaled by QSCALE) / K -> [bh][s][d], V -> [bh][d][s];
// mode 1: fp32 row-major out
// ---------------------------------------------------------------------------
__global__ __launch_bounds__(256) void gemm_mma(
    const __half* __restrict__ A, const __half* __restrict__ Bmat,
    const float* __restrict__ bias,
    __half* __restrict__ qo, __half* __restrict__ ko, __half* __restrict__ vo,
    float* __restrict__ out, int mode)
{
    extern __shared__ __half sm[];
    __half* As = sm;                        // 2 x [128][72]
    __half* Bs = sm + 2 * GBM * GP;         // 2 x [128][72]

    const int tid = threadIdx.x;
    const int wid = tid >> 5;
    const int L   = tid & 31;
    const int g   = L >> 2;
    const int t   = L & 3;
    const int wm0 = (wid & 1) * 64;
    const int wn0 = (wid >> 1) * 32;

    const int m0 = blockIdx.x * GBM;
    const int n0 = blockIdx.y * GBN;

    const __half* Ag = A + (size_t)m0 * En;
    const __half* Bg = Bmat + (size_t)n0 * En;

    const uint32_t sA = smem_u32(As);
    const uint32_t sB = smem_u32(Bs);

    auto issue = [&](int kc) {
        const int buf = kc & 1;
        const int k0 = kc * GBK;
        const uint32_t ab = sA + buf * (GBM * GP * 2);
        const uint32_t bb = sB + buf * (GBN * GP * 2);
        #pragma unroll
        for (int it = 0; it < 4; it++) {     // A: 128 rows x 8 granules(8h)
            int idx = tid + it * 256;
            int r = idx >> 3, c8 = idx & 7;
            cp16(ab + (uint32_t)(r * GP + c8 * 8) * 2, Ag + (size_t)r * En + k0 + c8 * 8);
        }
        #pragma unroll
        for (int it = 0; it < 4; it++) {     // B: 128 rows x 8 granules
            int idx = tid + it * 256;
            int r = idx >> 3, c8 = idx & 7;
            cp16(bb + (uint32_t)(r * GP + c8 * 8) * 2, Bg + (size_t)r * En + k0 + c8 * 8);
        }
        CP_COMMIT();
    };

    float acc[4][4][4] = {};

    issue(0);
    for (int kc = 0; kc < NC; kc++) {
        if (kc + 1 < NC) { issue(kc + 1); CP_WAIT1(); }
        else             { CP_WAIT0(); }
        __syncthreads();

        const __half* Ab = As + (kc & 1) * (GBM * GP);
        const __half* Bb = Bs + (kc & 1) * (GBN * GP);

        #pragma unroll
        for (int ks = 0; ks < 4; ks++) {     // GBK=64 / k16
            uint32_t bfr[4][2];
            #pragma unroll
            for (int nt = 0; nt < 4; nt++) {
                const __half* bp = Bb + (wn0 + nt * 8 + g) * GP + ks * 16 + 2 * t;
                bfr[nt][0] = ldh2(bp);
                bfr[nt][1] = ldh2(bp + 8);
            }
            #pragma unroll
            for (int mt = 0; mt < 4; mt++) {
                const __half* ap = Ab + (wm0 + mt * 16 + g) * GP + ks * 16 + 2 * t;
                uint32_t af[4];
                af[0] = ldh2(ap);
                af[1] = ldh2(ap + 8 * GP);
                af[2] = ldh2(ap + 8);
                af[3] = ldh2(ap + 8 * GP + 8);
                #pragma unroll
                for (int nt = 0; nt < 4; nt++) mma16(acc[mt][nt], af, bfr[nt]);
            }
        }
        __syncthreads();
    }

    // Epilogue
    #pragma unroll
    for (int mt = 0; mt < 4; mt++) {
        const int r1 = m0 + wm0 + mt * 16 + g;
        const int r2 = r1 + 8;
        #pragma unroll
        for (int nt = 0; nt < 4; nt++) {
            const int ntile = n0 + wn0 + nt * 8;
            const int col = ntile + 2 * t;
            const float2 bb2 = *(const float2*)(bias + col);
            float v0 = acc[mt][nt][0] + bb2.x;
            float v1 = acc[mt][nt][1] + bb2.y;
            float v2 = acc[mt][nt][2] + bb2.x;
            float v3 = acc[mt][nt][3] + bb2.y;
            if (mode == 0) {
                const int proj = ntile >> 10;
                const int h    = (ntile >> 6) & 15;
                const int d    = (ntile & 63) + 2 * t;
                const int b1 = r1 >> 11, s1 = r1 & 2047;
                const int b2 = r2 >> 11, s2 = r2 & 2047;
                const int bh1 = b1 * 16 + h, bh2 = b2 * 16 + h;
                if (proj == 0) {
                    *(__half2*)(qo + ((size_t)bh1 * Sn + s1) * Dn + d) =
                        __floats2half2_rn(v0 * QSCALE, v1 * QSCALE);
                    *(__half2*)(qo + ((size_t)bh2 * Sn + s2) * Dn + d) =
                        __floats2half2_rn(v2 * QSCALE, v3 * QSCALE);
                } else if (proj == 1) {
                    *(__half2*)(ko + ((size_t)bh1 * Sn + s1) * Dn + d) = __floats2half2_rn(v0, v1);
                    *(__half2*)(ko + ((size_t)bh2 * Sn + s2) * Dn + d) = __floats2half2_rn(v2, v3);
                } else {
                    vo[((size_t)bh1 * Dn + d)     * Sn + s1] = __float2half_rn(v0);
                    vo[((size_t)bh1 * Dn + d + 1) * Sn + s1] = __float2half_rn(v1);
                    vo[((size_t)bh2 * Dn + d)     * Sn + s2] = __float2half_rn(v2);
                    vo[((size_t)bh2 * Dn + d + 1) * Sn + s2] = __float2half_rn(v3);
                }
            } else {
                *(float2*)(out + (size_t)r1 * En + col) = make_float2(v0, v1);
                *(float2*)(out + (size_t)r2 * En + col) = make_float2(v2, v3);
            }
        }
    }
}

// ---------------------------------------------------------------------------
// Causal flash attention: fp16 MMA, 2-stage K/V double buffer.
// 128 threads; Q tile 128 = 4 warps x 32 rows (2 mt of 16); KV chunk 64.
// fp16x2 exp2 (one MUFU per pair); row sums via ones-MMA (no FADD, no shfl).
// ---------------------------------------------------------------------------
__global__ __launch_bounds__(128) void attn_mma(__half* __restrict__ ctx)
{
    extern __shared__ __half sm[];
    __half* Qs = sm;                         // [128][72]
    __half* Ks = sm + 128 * HPAD;            // 2 x [64][72] (rows = key)
    __half* Vt = sm + 128 * HPAD + 2 * KVH;  // 2 x [64][72] (rows = d)

    const int tid = threadIdx.x;
    const int w   = tid >> 5;
    const int L   = tid & 31;
    const int g   = L >> 2;
    const int t   = L & 3;

    const int bh = blockIdx.y;
    const int b  = bh >> 4;
    const int h  = bh & 15;
    const int i0 = (gridDim.x - 1 - blockIdx.x) * 128;

    const __half* Qp = g_Qh + (size_t)bh * Sn * Dn;
    const __half* Kp = g_Kh + (size_t)bh * Sn * Dn;
    const __half* Vp = g_Vth + (size_t)bh * Dn * Sn;

    const uint32_t sQ = smem_u32(Qs);
    const uint32_t sK = smem_u32(Ks);
    const uint32_t sV = smem_u32(Vt);

    auto issueKV = [&](int ch) {
        const uint32_t off = (uint32_t)(ch & 1) * (KVH * 2);
        const int j0 = ch * 64;
        #pragma unroll
        for (int it = 0; it < 4; it++) {     // K: 64 rows x 8 granules
            int idx = tid + it * 128;
            int r = idx >> 3, c8 = idx & 7;
            cp16(sK + off + (uint32_t)(r * HPAD + c8 * 8) * 2,
                 Kp + (size_t)(j0 + r) * Dn + c8 * 8);
        }
        #pragma unroll
        for (int it = 0; it < 4; it++) {     // V^T: 64 d-rows x 8 granules
            int idx = tid + it * 128;
            int r = idx >> 3, c8 = idx & 7;
            cp16(sV + off + (uint32_t)(r * HPAD + c8 * 8) * 2,
                 Vp + (size_t)r * Sn + j0 + c8 * 8);
        }
        CP_COMMIT();
    };

    #pragma unroll
    for (int it = 0; it < 8; it++) {         // Q: 128 rows x 8 granules
        int idx = tid + it * 128;
        int r = idx >> 3, c8 = idx & 7;
        cp16(sQ + (uint32_t)(r * HPAD + c8 * 8) * 2, Qp + (size_t)(i0 + r) * Dn + c8 * 8);
    }
    issueKV(0);

    const int qr0 = i0 + w * 32;             // warp's first query row (32 rows)

    float o[2][8][4] = {};
    float osum[2][4] = {};                   // MMA-computed row sums
    float mrow[2][2] = {{ -1e30f, -1e30f }, { -1e30f, -1e30f }};
    const uint32_t bones[2] = { ONES_H2, ONES_H2 };

    const int nch = i0 / 64 + 2;
    for (int ch = 0; ch < nch; ch++) {
        const int j0 = ch * 64;
        if (ch + 1 < nch) { issueKV(ch + 1); CP_WAIT1(); }
        else              { CP_WAIT0(); }
        __syncthreads();

        const __half* Kb = Ks + (ch & 1) * KVH;
        const __half* Vb = Vt + (ch & 1) * KVH;

        if (j0 <= qr0 + 31) {
            // ---- S = Q K^T (log2 domain via Q pre-scale) ----
            float sc[2][8][4] = {};
            #pragma unroll
            for (int ks = 0; ks < 4; ks++) {
                uint32_t qa[2][4];
                #pragma unroll
                for (int mt = 0; mt < 2; mt++) {
                    const __half* qp = Qs + (w * 32 + mt * 16 + g) * HPAD + ks * 16 + 2 * t;
                    qa[mt][0] = ldh2(qp);
                    qa[mt][1] = ldh2(qp + 8 * HPAD);
                    qa[mt][2] = ldh2(qp + 8);
                    qa[mt][3] = ldh2(qp + 8 * HPAD + 8);
                }
                #pragma unroll
                for (int nt = 0; nt < 8; nt++) {
                    const __half* kp = Kb + (nt * 8 + g) * HPAD + ks * 16 + 2 * t;
                    uint32_t bb[2];
                    bb[0] = ldh2(kp);
                    bb[1] = ldh2(kp + 8);
                    mma16(sc[0][nt], qa[0], bb);
                    mma16(sc[1][nt], qa[1], bb);
                }
            }

            // ---- causal mask + online max (exp2 domain, per mt) ----
            float cr[2][2];
            #pragma unroll
            for (int mt = 0; mt < 2; mt++) {
                const int r0g = qr0 + mt * 16 + g;
                const int r1g = r0g + 8;
                const bool needmask = (j0 + 63 > qr0 + mt * 16);
                if (needmask) {
                    #pragma unroll
                    for (int nt = 0; nt < 8; nt++) {
                        const int c0 = j0 + nt * 8 + 2 * t;
                        if (c0     > r0g) sc[mt][nt][0] = -1e30f;
                        if (c0 + 1 > r0g) sc[mt][nt][1] = -1e30f;
                        if (c0     > r1g) sc[mt][nt][2] = -1e30f;
                        if (c0 + 1 > r1g) sc[mt][nt][3] = -1e30f;
                    }
                }

                float mx0 = -1e30f, mx1 = -1e30f;
                #pragma unroll
                for (int nt = 0; nt < 8; nt++) {
                    mx0 = fmaxf(mx0, fmaxf(sc[mt][nt][0], sc[mt][nt][1]));
                    mx1 = fmaxf(mx1, fmaxf(sc[mt][nt][2], sc[mt][nt][3]));
                }
                mx0 = fmaxf(mx0, __shfl_xor_sync(0xffffffffu, mx0, 1));
                mx0 = fmaxf(mx0, __shfl_xor_sync(0xffffffffu, mx0, 2));
                mx1 = fmaxf(mx1, __shfl_xor_sync(0xffffffffu, mx1, 1));
                mx1 = fmaxf(mx1, __shfl_xor_sync(0xffffffffu, mx1, 2));

                const float m0n = fmaxf(mrow[mt][0], mx0);
                const float m1n = fmaxf(mrow[mt][1], mx1);
                cr[mt][0] = exp2f(mrow[mt][0] - m0n);
                cr[mt][1] = exp2f(mrow[mt][1] - m1n);
                mrow[mt][0] = m0n;
                mrow[mt][1] = m1n;

                // rescale O and sum accumulators
                #pragma unroll
                for (int nt = 0; nt < 8; nt++) {
                    o[mt][nt][0] *= cr[mt][0]; o[mt][nt][1] *= cr[mt][0];
                    o[mt][nt][2] *= cr[mt][1]; o[mt][nt][3] *= cr[mt][1];
                }
                osum[mt][0] *= cr[mt][0]; osum[mt][1] *= cr[mt][0];
                osum[mt][2] *= cr[mt][1]; osum[mt][3] *= cr[mt][1];
            }

            // ---- P = exp2(S - m) directly into fp16 A-fragments;
            //      O += P V and rowsum += P @ ones ----
            #pragma unroll
            for (int ks = 0; ks < 4; ks++) {
                uint32_t pa[2][4];
                #pragma unroll
                for (int mt = 0; mt < 2; mt++) {
                    const float m0 = mrow[mt][0];
                    const float m1 = mrow[mt][1];
                    pa[mt][0] = ex2h2(sc[mt][2*ks][0]   - m0, sc[mt][2*ks][1]   - m0);
                    pa[mt][1] = ex2h2(sc[mt][2*ks][2]   - m1, sc[mt][2*ks][3]   - m1);
                    pa[mt][2] = ex2h2(sc[mt][2*ks+1][0] - m0, sc[mt][2*ks+1][1] - m0);
                    pa[mt][3] = ex2h2(sc[mt][2*ks+1][2] - m1, sc[mt][2*ks+1][3] - m1);
                }
                #pragma unroll
                for (int nt = 0; nt < 8; nt++) {
                    const __half* vp = Vb + (nt * 8 + g) * HPAD + ks * 16 + 2 * t;
                    uint32_t bb[2];
                    bb[0] = ldh2(vp);
                    bb[1] = ldh2(vp + 8);
                    mma16(o[0][nt], pa[0], bb);
                    mma16(o[1][nt], pa[1], bb);
                }
                mma16(osum[0], pa[0], bones);
                mma16(osum[1], pa[1], bones);
            }
        }
        __syncthreads();
    }

    // ---- epilogue: normalize (sums complete per-lane via MMA), write ctx ----
    #pragma unroll
    for (int mt = 0; mt < 2; mt++) {
        const float inv0 = 1.f / osum[mt][0];
        const float inv1 = 1.f / osum[mt][2];
        const int s0g = qr0 + mt * 16 + g;
        const int s1g = s0g + 8;
        #pragma unroll
        for (int nt = 0; nt < 8; nt++) {
            const int d = nt * 8 + 2 * t;
            *(__half2*)(ctx + ((size_t)b * Sn + s0g) * En + h * Dn + d) =
                __floats2half2_rn(o[mt][nt][0] * inv0, o[mt][nt][1] * inv0);
            *(__half2*)(ctx + ((size_t)b * Sn + s1g) * En + h * Dn + d) =
                __floats2half2_rn(o[mt][nt][2] * inv1, o[mt][nt][3] * inv1);
        }
    }
}

// ---------------------------------------------------------------------------
extern "C" void kernel_launch(void* const* d_in, const int* in_sizes, int n_in,
                              void* d_out, int out_size)
{
    const float* x  = (const float*)d_in[0];
    const float* Wq = (const float*)d_in[1];
    const float* bq = (const float*)d_in[2];
    const float* Wk = (const float*)d_in[3];
    const float* bk = (const float*)d_in[4];
    const float* Wv = (const float*)d_in[5];
    const float* bv = (const float*)d_in[6];
    const float* Wo = (const float*)d_in[7];
    const float* bo = (const float*)d_in[8];
    float* out = (float*)d_out;

    __half *qh, *kh, *vth, *ctxh, *xh, *wth, *woh;
    float *biasv;
    cudaGetSymbolAddress((void**)&qh, g_Qh);
    cudaGetSymbolAddress((void**)&kh, g_Kh);
    cudaGetSymbolAddress((void**)&vth, g_Vth);
    cudaGetSymbolAddress((void**)&ctxh, g_ctxh);
    cudaGetSymbolAddress((void**)&xh, g_xh);
    cudaGetSymbolAddress((void**)&wth, g_Wth);
    cudaGetSymbolAddress((void**)&woh, g_Woh);
    cudaGetSymbolAddress((void**)&biasv, g_bias);

    const int gemm_smem = 2 * (GBM + GBN) * GP * 2;          // 73728 B
    const int attn_smem = (128 * HPAD + 4 * 64 * HPAD) * 2;  // 55296 B
    cudaFuncSetAttribute(gemm_mma, cudaFuncAttributeMaxDynamicSharedMemorySize, gemm_smem);
    cudaFuncSetAttribute(attn_mma, cudaFuncAttributeMaxDynamicSharedMemorySize, attn_smem);

    prep_x <<<(Mn * En) / 1024, 256>>>(x);
    prep_w <<<(NTOT * En) / 256, 256>>>(Wq, bq, Wk, bk, Wv, bv);
    prep_wo<<<(En * En) / 1024, 256>>>(Wo);

    gemm_mma<<<dim3(Mn / GBM, NTOT / GBN), 256, gemm_smem>>>(
        xh, wth, biasv, qh, kh, vth, nullptr, 0);
    attn_mma<<<dim3(Sn / 128, BHn), 128, attn_smem>>>(ctxh);
    gemm_mma<<<dim3(Mn / GBM, En / GBN), 256, gemm_smem>>>(
        ctxh, woh, bo, nullptr, nullptr, nullptr, out, 1);
}

// round 16
// speedup vs baseline: 1.3245x; 1.0253x over previous
#include <cuda_runtime.h>
#include <cuda_fp16.h>
#include <cstdint>

// Problem constants
#define Bn 4
#define Sn 2048
#define En 1024
#define Hn 16
#define Dn 64
#define BHn (Bn*Hn)     // 64
#define Mn  (Bn*Sn)     // 8192
#define NTOT 3072       // 3 projections * H * D

// GEMM tile config (round-8 proven): block 128x128, 8 warps of 64x32, GBK=64
#define GBM 128
#define GBN 128
#define GBK 64
#define NC (En/GBK)     // 16 k-chunks
#define GP 72           // gemm smem row stride (halves)

// Attention (round-9 proven shape): Q tile 128, 4 warps x 32 rows; KV chunk 64
#define HPAD 72
#define KVH (64 * HPAD)

// Q pre-scale: (1/sqrt(64)) * log2(e), folded into Q at QKV epilogue
#define QSCALE 0.1803368801111204f
// packed half2 {1.0, 1.0}
#define ONES_H2 0x3C003C00u

// Scratch (allocation-free rule: __device__ globals)
__device__ __align__(256) __half g_Qh [(size_t)BHn * Sn * Dn];  // 16 MB
__device__ __align__(256) __half g_Kh [(size_t)BHn * Sn * Dn];  // 16 MB
__device__ __align__(256) __half g_Vth[(size_t)BHn * Dn * Sn];  // 16 MB (d-major)
__device__ __align__(256) __half g_ctxh[(size_t)Mn * En];       // 16 MB
__device__ __align__(256) __half g_xh [(size_t)Mn * En];        // 16 MB
__device__ __align__(256) __half g_Wth[(size_t)NTOT * En];      // 6 MB (K-major)
__device__ __align__(256) __half g_Woh[(size_t)En * En];        // 2 MB
__device__ __align__(256) float  g_bias[NTOT];

// ---------------------------------------------------------------------------
// Helpers
// ---------------------------------------------------------------------------
__device__ __forceinline__ uint32_t smem_u32(const void* p) {
    return (uint32_t)__cvta_generic_to_shared(p);
}
__device__ __forceinline__ void cp16(uint32_t dst, const void* src) {
    asm volatile("cp.async.cg.shared.global [%0], [%1], 16;" :: "r"(dst), "l"(src));
}
#define CP_COMMIT() asm volatile("cp.async.commit_group;" ::: "memory")
#define CP_WAIT1()  asm volatile("cp.async.wait_group 1;" ::: "memory")
#define CP_WAIT0()  asm volatile("cp.async.wait_group 0;" ::: "memory")

__device__ __forceinline__ uint32_t ldh2(const __half* p) {
    return *(const uint32_t*)p;
}
__device__ __forceinline__ uint32_t packh2(float lo, float hi) {
    __half2 h = __floats2half2_rn(lo, hi);
    return *(uint32_t*)&h;
}
// pack (lo,hi) to half2, then exp2 both halves in one MUFU op
__device__ __forceinline__ uint32_t ex2h2(float lo, float hi) {
    uint32_t p = packh2(lo, hi);
    uint32_t r;
    asm("ex2.approx.f16x2 %0, %1;" : "=r"(r) : "r"(p));
    return r;
}

// m16n8k16 fp16 MMA, fp32 accum (layout validated rounds 5-8)
__device__ __forceinline__ void mma16(float* c, const uint32_t* a, const uint32_t* b) {
    asm volatile("mma.sync.aligned.m16n8k16.row.col.f32.f16.f16.f32 "
        "{%0,%1,%2,%3}, {%4,%5,%6,%7}, {%8,%9}, {%0,%1,%2,%3};"
        : "+f"(c[0]), "+f"(c[1]), "+f"(c[2]), "+f"(c[3])
        : "r"(a[0]), "r"(a[1]), "r"(a[2]), "r"(a[3]), "r"(b[0]), "r"(b[1]));
}

// ---------------------------------------------------------------------------
// Prep kernels
// ---------------------------------------------------------------------------
__global__ __launch_bounds__(256) void prep_x(const float* __restrict__ x) {
    size_t i = ((size_t)blockIdx.x * 256 + threadIdx.x) * 4;
    float4 v = *(const float4*)(x + i);
    *(__half2*)(g_xh + i)     = __floats2half2_rn(v.x, v.y);
    *(__half2*)(g_xh + i + 2) = __floats2half2_rn(v.z, v.w);
}

// Coalesced weight transpose: W[h][e][d] -> g_Wth[(p*16+h)*64+d][e]
// Grid: (NTOT/32, En/32); block 256 = 8 e-rows x 32 d-cols per iteration.
__global__ __launch_bounds__(256) void prep_w(
    const float* __restrict__ Wq, const float* __restrict__ bq,
    const float* __restrict__ Wk, const float* __restrict__ bk,
    const float* __restrict__ Wv, const float* __restrict__ bv)
{
    __shared__ float tile[32][33];

    const int n0 = blockIdx.x * 32;          // n = (p*16+h)*64 + d
    const int e0 = blockIdx.y * 32;
    const int p  = n0 >> 10;
    const int h  = (n0 >> 6) & 15;
    const int d0 = n0 & 63;                  // 32-aligned within [0,64)

    const float* W = (p == 0) ? Wq : ((p == 1) ? Wk : Wv);
    const float* Wbase = W + ((size_t)h * En) * Dn;

    const int dl = threadIdx.x & 31;         // d_local
    const int el = threadIdx.x >> 5;         // e_local base (0..7)

    #pragma unroll
    for (int it = 0; it < 4; it++) {
        const int e = e0 + el + it * 8;
        tile[dl][el + it * 8] = Wbase[(size_t)e * Dn + d0 + dl];   // coalesced in d
    }
    __syncthreads();

    const int nl = threadIdx.x >> 5;         // n_local base (d index)
    const int ew = threadIdx.x & 31;         // e_local
    #pragma unroll
    for (int it = 0; it < 4; it++) {
        const int nn = nl + it * 8;
        g_Wth[(size_t)(n0 + nn) * En + e0 + ew] =
            __float2half_rn(tile[nn][ew]);                         // coalesced in e
    }

    if (e0 == 0 && threadIdx.x < 32) {
        const int n = n0 + threadIdx.x;
        const int db = n & 63;
        const float* bb = (p == 0) ? bq : ((p == 1) ? bk : bv);
        g_bias[n] = bb[h * Dn + db];
    }
}

__global__ __launch_bounds__(256) void prep_wo(const float* __restrict__ Wo) {
    size_t i = ((size_t)blockIdx.x * 256 + threadIdx.x) * 4;
    float4 v = *(const float4*)(Wo + i);
    *(__half2*)(g_Woh + i)     = __floats2half2_rn(v.x, v.y);
    *(__half2*)(g_Woh + i + 2) = __floats2half2_rn(v.z, v.w);
}

// ---------------------------------------------------------------------------
// fp16 warp-MMA GEMM (round-8 exact): 256 thr; 128x128; 8 warps 64x32; GBK=64
// mode 0: Q (pre-scaled by QSCALE) / K -> [bh][s][d], V -> [bh][d][s];
// mode 1: fp32 row-major out
// ---------------------------------------------------------------------------
__global__ __launch_bounds__(256) void gemm_mma(
    const __half* __restrict__ A, const __half* __restrict__ Bmat,
    const float* __restrict__ bias,
    __half* __restrict__ qo, __half* __restrict__ ko, __half* __restrict__ vo,
    float* __restrict__ out, int mode)
{
    extern __shared__ __half sm[];
    __half* As = sm;                        // 2 x [128][72]
    __half* Bs = sm + 2 * GBM * GP;         // 2 x [128][72]

    const int tid = threadIdx.x;
    const int wid = tid >> 5;
    const int L   = tid & 31;
    const int g   = L >> 2;
    const int t   = L & 3;
    const int wm0 = (wid & 1) * 64;
    const int wn0 = (wid >> 1) * 32;

    const int m0 = blockIdx.x * GBM;
    const int n0 = blockIdx.y * GBN;

    const __half* Ag = A + (size_t)m0 * En;
    const __half* Bg = Bmat + (size_t)n0 * En;

    const uint32_t sA = smem_u32(As);
    const uint32_t sB = smem_u32(Bs);

    auto issue = [&](int kc) {
        const int buf = kc & 1;
        const int k0 = kc * GBK;
        const uint32_t ab = sA + buf * (GBM * GP * 2);
        const uint32_t bb = sB + buf * (GBN * GP * 2);
        #pragma unroll
        for (int it = 0; it < 4; it++) {     // A: 128 rows x 8 granules(8h)
            int idx = tid + it * 256;
            int r = idx >> 3, c8 = idx & 7;
            cp16(ab + (uint32_t)(r * GP + c8 * 8) * 2, Ag + (size_t)r * En + k0 + c8 * 8);
        }
        #pragma unroll
        for (int it = 0; it < 4; it++) {     // B: 128 rows x 8 granules
            int idx = tid + it * 256;
            int r = idx >> 3, c8 = idx & 7;
            cp16(bb + (uint32_t)(r * GP + c8 * 8) * 2, Bg + (size_t)r * En + k0 + c8 * 8);
        }
        CP_COMMIT();
    };

    float acc[4][4][4] = {};

    issue(0);
    for (int kc = 0; kc < NC; kc++) {
        if (kc + 1 < NC) { issue(kc + 1); CP_WAIT1(); }
        else             { CP_WAIT0(); }
        __syncthreads();

        const __half* Ab = As + (kc & 1) * (GBM * GP);
        const __half* Bb = Bs + (kc & 1) * (GBN * GP);

        #pragma unroll
        for (int ks = 0; ks < 4; ks++) {     // GBK=64 / k16
            uint32_t bfr[4][2];
            #pragma unroll
            for (int nt = 0; nt < 4; nt++) {
                const __half* bp = Bb + (wn0 + nt * 8 + g) * GP + ks * 16 + 2 * t;
                bfr[nt][0] = ldh2(bp);
                bfr[nt][1] = ldh2(bp + 8);
            }
            #pragma unroll
            for (int mt = 0; mt < 4; mt++) {
                const __half* ap = Ab + (wm0 + mt * 16 + g) * GP + ks * 16 + 2 * t;
                uint32_t af[4];
                af[0] = ldh2(ap);
                af[1] = ldh2(ap + 8 * GP);
                af[2] = ldh2(ap + 8);
                af[3] = ldh2(ap + 8 * GP + 8);
                #pragma unroll
                for (int nt = 0; nt < 4; nt++) mma16(acc[mt][nt], af, bfr[nt]);
            }
        }
        __syncthreads();
    }

    // Epilogue
    #pragma unroll
    for (int mt = 0; mt < 4; mt++) {
        const int r1 = m0 + wm0 + mt * 16 + g;
        const int r2 = r1 + 8;
        #pragma unroll
        for (int nt = 0; nt < 4; nt++) {
            const int ntile = n0 + wn0 + nt * 8;
            const int col = ntile + 2 * t;
            const float2 bb2 = *(const float2*)(bias + col);
            float v0 = acc[mt][nt][0] + bb2.x;
            float v1 = acc[mt][nt][1] + bb2.y;
            float v2 = acc[mt][nt][2] + bb2.x;
            float v3 = acc[mt][nt][3] + bb2.y;
            if (mode == 0) {
                const int proj = ntile >> 10;
                const int h    = (ntile >> 6) & 15;
                const int d    = (ntile & 63) + 2 * t;
                const int b1 = r1 >> 11, s1 = r1 & 2047;
                const int b2 = r2 >> 11, s2 = r2 & 2047;
                const int bh1 = b1 * 16 + h, bh2 = b2 * 16 + h;
                if (proj == 0) {
                    *(__half2*)(qo + ((size_t)bh1 * Sn + s1) * Dn + d) =
                        __floats2half2_rn(v0 * QSCALE, v1 * QSCALE);
                    *(__half2*)(qo + ((size_t)bh2 * Sn + s2) * Dn + d) =
                        __floats2half2_rn(v2 * QSCALE, v3 * QSCALE);
                } else if (proj == 1) {
                    *(__half2*)(ko + ((size_t)bh1 * Sn + s1) * Dn + d) = __floats2half2_rn(v0, v1);
                    *(__half2*)(ko + ((size_t)bh2 * Sn + s2) * Dn + d) = __floats2half2_rn(v2, v3);
                } else {
                    vo[((size_t)bh1 * Dn + d)     * Sn + s1] = __float2half_rn(v0);
                    vo[((size_t)bh1 * Dn + d + 1) * Sn + s1] = __float2half_rn(v1);
                    vo[((size_t)bh2 * Dn + d)     * Sn + s2] = __float2half_rn(v2);
                    vo[((size_t)bh2 * Dn + d + 1) * Sn + s2] = __float2half_rn(v3);
                }
            } else {
                *(float2*)(out + (size_t)r1 * En + col) = make_float2(v0, v1);
                *(float2*)(out + (size_t)r2 * En + col) = make_float2(v2, v3);
            }
        }
    }
}

// ---------------------------------------------------------------------------
// Causal flash attention: fp16 MMA, 2-stage K/V double buffer.
// 128 threads; Q tile 128 = 4 warps x 32 rows (2 mt of 16); KV chunk 64.
// fp16x2 exp2; row sums via ones-MMA.
// ---------------------------------------------------------------------------
__global__ __launch_bounds__(128) void attn_mma(__half* __restrict__ ctx)
{
    extern __shared__ __half sm[];
    __half* Qs = sm;                         // [128][72]
    __half* Ks = sm + 128 * HPAD;            // 2 x [64][72] (rows = key)
    __half* Vt = sm + 128 * HPAD + 2 * KVH;  // 2 x [64][72] (rows = d)

    const int tid = threadIdx.x;
    const int w   = tid >> 5;
    const int L   = tid & 31;
    const int g   = L >> 2;
    const int t   = L & 3;

    const int bh = blockIdx.y;
    const int b  = bh >> 4;
    const int h  = bh & 15;
    const int i0 = (gridDim.x - 1 - blockIdx.x) * 128;

    const __half* Qp = g_Qh + (size_t)bh * Sn * Dn;
    const __half* Kp = g_Kh + (size_t)bh * Sn * Dn;
    const __half* Vp = g_Vth + (size_t)bh * Dn * Sn;

    const uint32_t sQ = smem_u32(Qs);
    const uint32_t sK = smem_u32(Ks);
    const uint32_t sV = smem_u32(Vt);

    auto issueKV = [&](int ch) {
        const uint32_t off = (uint32_t)(ch & 1) * (KVH * 2);
        const int j0 = ch * 64;
        #pragma unroll
        for (int it = 0; it < 4; it++) {     // K: 64 rows x 8 granules
            int idx = tid + it * 128;
            int r = idx >> 3, c8 = idx & 7;
            cp16(sK + off + (uint32_t)(r * HPAD + c8 * 8) * 2,
                 Kp + (size_t)(j0 + r) * Dn + c8 * 8);
        }
        #pragma unroll
        for (int it = 0; it < 4; it++) {     // V^T: 64 d-rows x 8 granules
            int idx = tid + it * 128;
            int r = idx >> 3, c8 = idx & 7;
            cp16(sV + off + (uint32_t)(r * HPAD + c8 * 8) * 2,
                 Vp + (size_t)r * Sn + j0 + c8 * 8);
        }
        CP_COMMIT();
    };

    #pragma unroll
    for (int it = 0; it < 8; it++) {         // Q: 128 rows x 8 granules
        int idx = tid + it * 128;
        int r = idx >> 3, c8 = idx & 7;
        cp16(sQ + (uint32_t)(r * HPAD + c8 * 8) * 2, Qp + (size_t)(i0 + r) * Dn + c8 * 8);
    }
    issueKV(0);

    const int qr0 = i0 + w * 32;             // warp's first query row (32 rows)

    float o[2][8][4] = {};
    float osum[2][4] = {};                   // MMA-computed row sums
    float mrow[2][2] = {{ -1e30f, -1e30f }, { -1e30f, -1e30f }};
    const uint32_t bones[2] = { ONES_H2, ONES_H2 };

    const int nch = i0 / 64 + 2;
    for (int ch = 0; ch < nch; ch++) {
        const int j0 = ch * 64;
        if (ch + 1 < nch) { issueKV(ch + 1); CP_WAIT1(); }
        else              { CP_WAIT0(); }
        __syncthreads();

        const __half* Kb = Ks + (ch & 1) * KVH;
        const __half* Vb = Vt + (ch & 1) * KVH;

        if (j0 <= qr0 + 31) {
            // ---- S = Q K^T (log2 domain via Q pre-scale) ----
            float sc[2][8][4] = {};
            #pragma unroll
            for (int ks = 0; ks < 4; ks++) {
                uint32_t qa[2][4];
                #pragma unroll
                for (int mt = 0; mt < 2; mt++) {
                    const __half* qp = Qs + (w * 32 + mt * 16 + g) * HPAD + ks * 16 + 2 * t;
                    qa[mt][0] = ldh2(qp);
                    qa[mt][1] = ldh2(qp + 8 * HPAD);
                    qa[mt][2] = ldh2(qp + 8);
                    qa[mt][3] = ldh2(qp + 8 * HPAD + 8);
                }
                #pragma unroll
                for (int nt = 0; nt < 8; nt++) {
                    const __half* kp = Kb + (nt * 8 + g) * HPAD + ks * 16 + 2 * t;
                    uint32_t bb[2];
                    bb[0] = ldh2(kp);
                    bb[1] = ldh2(kp + 8);
                    mma16(sc[0][nt], qa[0], bb);
                    mma16(sc[1][nt], qa[1], bb);
                }
            }

            // ---- causal mask + online max (exp2 domain, per mt) ----
            float cr[2][2];
            #pragma unroll
            for (int mt = 0; mt < 2; mt++) {
                const int r0g = qr0 + mt * 16 + g;
                const int r1g = r0g + 8;
                const bool needmask = (j0 + 63 > qr0 + mt * 16);
                if (needmask) {
                    #pragma unroll
                    for (int nt = 0; nt < 8; nt++) {
                        const int c0 = j0 + nt * 8 + 2 * t;
                        if (c0     > r0g) sc[mt][nt][0] = -1e30f;
                        if (c0 + 1 > r0g) sc[mt][nt][1] = -1e30f;
                        if (c0     > r1g) sc[mt][nt][2] = -1e30f;
                        if (c0 + 1 > r1g) sc[mt][nt][3] = -1e30f;
                    }
                }

                float mx0 = -1e30f, mx1 = -1e30f;
                #pragma unroll
                for (int nt = 0; nt < 8; nt++) {
                    mx0 = fmaxf(mx0, fmaxf(sc[mt][nt][0], sc[mt][nt][1]));
                    mx1 = fmaxf(mx1, fmaxf(sc[mt][nt][2], sc[mt][nt][3]));
                }
                mx0 = fmaxf(mx0, __shfl_xor_sync(0xffffffffu, mx0, 1));
                mx0 = fmaxf(mx0, __shfl_xor_sync(0xffffffffu, mx0, 2));
                mx1 = fmaxf(mx1, __shfl_xor_sync(0xffffffffu, mx1, 1));
                mx1 = fmaxf(mx1, __shfl_xor_sync(0xffffffffu, mx1, 2));

                const float m0n = fmaxf(mrow[mt][0], mx0);
                const float m1n = fmaxf(mrow[mt][1], mx1);
                cr[mt][0] = exp2f(mrow[mt][0] - m0n);
                cr[mt][1] = exp2f(mrow[mt][1] - m1n);
                mrow[mt][0] = m0n;
                mrow[mt][1] = m1n;

                #pragma unroll
                for (int nt = 0; nt < 8; nt++) {
                    o[mt][nt][0] *= cr[mt][0]; o[mt][nt][1] *= cr[mt][0];
                    o[mt][nt][2] *= cr[mt][1]; o[mt][nt][3] *= cr[mt][1];
                }
                osum[mt][0] *= cr[mt][0]; osum[mt][1] *= cr[mt][0];
                osum[mt][2] *= cr[mt][1]; osum[mt][3] *= cr[mt][1];
            }

            // ---- P = exp2(S - m) into fp16 A-frags; O += P V; rowsum += P@1 ----
            #pragma unroll
            for (int ks = 0; ks < 4; ks++) {
                uint32_t pa[2][4];
                #pragma unroll
                for (int mt = 0; mt < 2; mt++) {
                    const float m0 = mrow[mt][0];
                    const float m1 = mrow[mt][1];
                    pa[mt][0] = ex2h2(sc[mt][2*ks][0]   - m0, sc[mt][2*ks][1]   - m0);
                    pa[mt][1] = ex2h2(sc[mt][2*ks][2]   - m1, sc[mt][2*ks][3]   - m1);
                    pa[mt][2] = ex2h2(sc[mt][2*ks+1][0] - m0, sc[mt][2*ks+1][1] - m0);
                    pa[mt][3] = ex2h2(sc[mt][2*ks+1][2] - m1, sc[mt][2*ks+1][3] - m1);
                }
                #pragma unroll
                for (int nt = 0; nt < 8; nt++) {
                    const __half* vp = Vb + (nt * 8 + g) * HPAD + ks * 16 + 2 * t;
                    uint32_t bb[2];
                    bb[0] = ldh2(vp);
                    bb[1] = ldh2(vp + 8);
                    mma16(o[0][nt], pa[0], bb);
                    mma16(o[1][nt], pa[1], bb);
                }
                mma16(osum[0], pa[0], bones);
                mma16(osum[1], pa[1], bones);
            }
        }
        __syncthreads();
    }

    // ---- epilogue: normalize, write ctx ----
    #pragma unroll
    for (int mt = 0; mt < 2; mt++) {
        const float inv0 = 1.f / osum[mt][0];
        const float inv1 = 1.f / osum[mt][2];
        const int s0g = qr0 + mt * 16 + g;
        const int s1g = s0g + 8;
        #pragma unroll
        for (int nt = 0; nt < 8; nt++) {
            const int d = nt * 8 + 2 * t;
            *(__half2*)(ctx + ((size_t)b * Sn + s0g) * En + h * Dn + d) =
                __floats2half2_rn(o[mt][nt][0] * inv0, o[mt][nt][1] * inv0);
            *(__half2*)(ctx + ((size_t)b * Sn + s1g) * En + h * Dn + d) =
                __floats2half2_rn(o[mt][nt][2] * inv1, o[mt][nt][3] * inv1);
        }
    }
}

// ---------------------------------------------------------------------------
extern "C" void kernel_launch(void* const* d_in, const int* in_sizes, int n_in,
                              void* d_out, int out_size)
{
    const float* x  = (const float*)d_in[0];
    const float* Wq = (const float*)d_in[1];
    const float* bq = (const float*)d_in[2];
    const float* Wk = (const float*)d_in[3];
    const float* bk = (const float*)d_in[4];
    const float* Wv = (const float*)d_in[5];
    const float* bv = (const float*)d_in[6];
    const float* Wo = (const float*)d_in[7];
    const float* bo = (const float*)d_in[8];
    float* out = (float*)d_out;

    __half *qh, *kh, *vth, *ctxh, *xh, *wth, *woh;
    float *biasv;
    cudaGetSymbolAddress((void**)&qh, g_Qh);
    cudaGetSymbolAddress((void**)&kh, g_Kh);
    cudaGetSymbolAddress((void**)&vth, g_Vth);
    cudaGetSymbolAddress((void**)&ctxh, g_ctxh);
    cudaGetSymbolAddress((void**)&xh, g_xh);
    cudaGetSymbolAddress((void**)&wth, g_Wth);
    cudaGetSymbolAddress((void**)&woh, g_Woh);
    cudaGetSymbolAddress((void**)&biasv, g_bias);

    const int gemm_smem = 2 * (GBM + GBN) * GP * 2;          // 73728 B
    const int attn_smem = (128 * HPAD + 4 * 64 * HPAD) * 2;  // 55296 B
    cudaFuncSetAttribute(gemm_mma, cudaFuncAttributeMaxDynamicSharedMemorySize, gemm_smem);
    cudaFuncSetAttribute(attn_mma, cudaFuncAttributeMaxDynamicSharedMemorySize, attn_smem);

    prep_x <<<(Mn * En) / 1024, 256>>>(x);
    prep_w <<<dim3(NTOT / 32, En / 32), 256>>>(Wq, bq, Wk, bk, Wv, bv);
    prep_wo<<<(En * En) / 1024, 256>>>(Wo);

    gemm_mma<<<dim3(Mn / GBM, NTOT / GBN), 256, gemm_smem>>>(
        xh, wth, biasv, qh, kh, vth, nullptr, 0);
    attn_mma<<<dim3(Sn / 128, BHn), 128, attn_smem>>>(ctxh);
    gemm_mma<<<dim3(Mn / GBM, En / GBN), 256, gemm_smem>>>(
        ctxh, woh, bo, nullptr, nullptr, nullptr, out, 1);
}

// round 17
// speedup vs baseline: 1.3326x; 1.0061x over previous
#include <cuda_runtime.h>
#include <cuda_fp16.h>
#include <cstdint>

// Problem constants
#define Bn 4
#define Sn 2048
#define En 1024
#define Hn 16
#define Dn 64
#define BHn (Bn*Hn)     // 64
#define Mn  (Bn*Sn)     // 8192
#define NTOT 3072       // 3 projections * H * D

// GEMM tile config (round-8 proven): block 128x128, 8 warps of 64x32, GBK=64
#define GBM 128
#define GBN 128
#define GBK 64
#define NC (En/GBK)     // 16 k-chunks
#define GP 72           // gemm smem row stride (halves)

// Attention (round-9 proven shape): Q tile 128, 4 warps x 32 rows; KV chunk 64
#define HPAD 72
#define KVH (64 * HPAD)

// Q pre-scale: (1/sqrt(64)) * log2(e), folded into Q at QKV epilogue
#define QSCALE 0.1803368801111204f
// packed half2 {1.0, 1.0}
#define ONES_H2 0x3C003C00u

// Scratch (allocation-free rule: __device__ globals)
__device__ __align__(256) __half g_Qh [(size_t)BHn * Sn * Dn];  // 16 MB
__device__ __align__(256) __half g_Kh [(size_t)BHn * Sn * Dn];  // 16 MB
__device__ __align__(256) __half g_Vth[(size_t)BHn * Dn * Sn];  // 16 MB (d-major)
__device__ __align__(256) __half g_ctxh[(size_t)Mn * En];       // 16 MB
__device__ __align__(256) __half g_xh [(size_t)Mn * En];        // 16 MB
__device__ __align__(256) __half g_Wth[(size_t)NTOT * En];      // 6 MB (K-major)
__device__ __align__(256) __half g_Woh[(size_t)En * En];        // 2 MB
__device__ __align__(256) float  g_bias[NTOT];

// ---------------------------------------------------------------------------
// Helpers
// ---------------------------------------------------------------------------
__device__ __forceinline__ uint32_t smem_u32(const void* p) {
    return (uint32_t)__cvta_generic_to_shared(p);
}
__device__ __forceinline__ void cp16(uint32_t dst, const void* src) {
    asm volatile("cp.async.cg.shared.global [%0], [%1], 16;" :: "r"(dst), "l"(src));
}
#define CP_COMMIT() asm volatile("cp.async.commit_group;" ::: "memory")
#define CP_WAIT1()  asm volatile("cp.async.wait_group 1;" ::: "memory")
#define CP_WAIT0()  asm volatile("cp.async.wait_group 0;" ::: "memory")

__device__ __forceinline__ uint32_t ldh2(const __half* p) {
    return *(const uint32_t*)p;
}
__device__ __forceinline__ uint32_t packh2(float lo, float hi) {
    __half2 h = __floats2half2_rn(lo, hi);
    return *(uint32_t*)&h;
}
// pack (lo,hi) to half2, then exp2 both halves in one MUFU op
__device__ __forceinline__ uint32_t ex2h2(float lo, float hi) {
    uint32_t p = packh2(lo, hi);
    uint32_t r;
    asm("ex2.approx.f16x2 %0, %1;" : "=r"(r) : "r"(p));
    return r;
}

// m16n8k16 fp16 MMA, fp32 accum (layout validated rounds 5-8)
__device__ __forceinline__ void mma16(float* c, const uint32_t* a, const uint32_t* b) {
    asm volatile("mma.sync.aligned.m16n8k16.row.col.f32.f16.f16.f32 "
        "{%0,%1,%2,%3}, {%4,%5,%6,%7}, {%8,%9}, {%0,%1,%2,%3};"
        : "+f"(c[0]), "+f"(c[1]), "+f"(c[2]), "+f"(c[3])
        : "r"(a[0]), "r"(a[1]), "r"(a[2]), "r"(a[3]), "r"(b[0]), "r"(b[1]));
}

// ---------------------------------------------------------------------------
// Prep kernels
// ---------------------------------------------------------------------------
// Merged x + Wo conversion (both plain f32 -> f16 elementwise)
__global__ __launch_bounds__(256) void prep_xw(const float* __restrict__ x,
                                               const float* __restrict__ Wo)
{
    size_t i = ((size_t)blockIdx.x * 256 + threadIdx.x) * 4;
    if (i < (size_t)Mn * En) {
        float4 v = *(const float4*)(x + i);
        *(__half2*)(g_xh + i)     = __floats2half2_rn(v.x, v.y);
        *(__half2*)(g_xh + i + 2) = __floats2half2_rn(v.z, v.w);
    } else {
        size_t j = i - (size_t)Mn * En;
        float4 v = *(const float4*)(Wo + j);
        *(__half2*)(g_Woh + j)     = __floats2half2_rn(v.x, v.y);
        *(__half2*)(g_Woh + j + 2) = __floats2half2_rn(v.z, v.w);
    }
}

// Coalesced weight transpose: W[h][e][d] -> g_Wth[(p*16+h)*64+d][e]
__global__ __launch_bounds__(256) void prep_w(
    const float* __restrict__ Wq, const float* __restrict__ bq,
    const float* __restrict__ Wk, const float* __restrict__ bk,
    const float* __restrict__ Wv, const float* __restrict__ bv)
{
    __shared__ float tile[32][33];

    const int n0 = blockIdx.x * 32;          // n = (p*16+h)*64 + d
    const int e0 = blockIdx.y * 32;
    const int p  = n0 >> 10;
    const int h  = (n0 >> 6) & 15;
    const int d0 = n0 & 63;

    const float* W = (p == 0) ? Wq : ((p == 1) ? Wk : Wv);
    const float* Wbase = W + ((size_t)h * En) * Dn;

    const int dl = threadIdx.x & 31;
    const int el = threadIdx.x >> 5;

    #pragma unroll
    for (int it = 0; it < 4; it++) {
        const int e = e0 + el + it * 8;
        tile[dl][el + it * 8] = Wbase[(size_t)e * Dn + d0 + dl];
    }
    __syncthreads();

    const int nl = threadIdx.x >> 5;
    const int ew = threadIdx.x & 31;
    #pragma unroll
    for (int it = 0; it < 4; it++) {
        const int nn = nl + it * 8;
        g_Wth[(size_t)(n0 + nn) * En + e0 + ew] = __float2half_rn(tile[nn][ew]);
    }

    if (e0 == 0 && threadIdx.x < 32) {
        const int n = n0 + threadIdx.x;
        const int db = n & 63;
        const float* bb = (p == 0) ? bq : ((p == 1) ? bk : bv);
        g_bias[n] = bb[h * Dn + db];
    }
}

// ---------------------------------------------------------------------------
// fp16 warp-MMA GEMM (round-8 exact): 256 thr; 128x128; 8 warps 64x32; GBK=64
// ---------------------------------------------------------------------------
__global__ __launch_bounds__(256) void gemm_mma(
    const __half* __restrict__ A, const __half* __restrict__ Bmat,
    const float* __restrict__ bias,
    __half* __restrict__ qo, __half* __restrict__ ko, __half* __restrict__ vo,
    float* __restrict__ out, int mode)
{
    extern __shared__ __half sm[];
    __half* As = sm;                        // 2 x [128][72]
    __half* Bs = sm + 2 * GBM * GP;         // 2 x [128][72]

    const int tid = threadIdx.x;
    const int wid = tid >> 5;
    const int L   = tid & 31;
    const int g   = L >> 2;
    const int t   = L & 3;
    const int wm0 = (wid & 1) * 64;
    const int wn0 = (wid >> 1) * 32;

    const int m0 = blockIdx.x * GBM;
    const int n0 = blockIdx.y * GBN;

    const __half* Ag = A + (size_t)m0 * En;
    const __half* Bg = Bmat + (size_t)n0 * En;

    const uint32_t sA = smem_u32(As);
    const uint32_t sB = smem_u32(Bs);

    auto issue = [&](int kc) {
        const int buf = kc & 1;
        const int k0 = kc * GBK;
        const uint32_t ab = sA + buf * (GBM * GP * 2);
        const uint32_t bb = sB + buf * (GBN * GP * 2);
        #pragma unroll
        for (int it = 0; it < 4; it++) {
            int idx = tid + it * 256;
            int r = idx >> 3, c8 = idx & 7;
            cp16(ab + (uint32_t)(r * GP + c8 * 8) * 2, Ag + (size_t)r * En + k0 + c8 * 8);
        }
        #pragma unroll
        for (int it = 0; it < 4; it++) {
            int idx = tid + it * 256;
            int r = idx >> 3, c8 = idx & 7;
            cp16(bb + (uint32_t)(r * GP + c8 * 8) * 2, Bg + (size_t)r * En + k0 + c8 * 8);
        }
        CP_COMMIT();
    };

    float acc[4][4][4] = {};

    issue(0);
    for (int kc = 0; kc < NC; kc++) {
        if (kc + 1 < NC) { issue(kc + 1); CP_WAIT1(); }
        else             { CP_WAIT0(); }
        __syncthreads();

        const __half* Ab = As + (kc & 1) * (GBM * GP);
        const __half* Bb = Bs + (kc & 1) * (GBN * GP);

        #pragma unroll
        for (int ks = 0; ks < 4; ks++) {
            uint32_t bfr[4][2];
            #pragma unroll
            for (int nt = 0; nt < 4; nt++) {
                const __half* bp = Bb + (wn0 + nt * 8 + g) * GP + ks * 16 + 2 * t;
                bfr[nt][0] = ldh2(bp);
                bfr[nt][1] = ldh2(bp + 8);
            }
            #pragma unroll
            for (int mt = 0; mt < 4; mt++) {
                const __half* ap = Ab + (wm0 + mt * 16 + g) * GP + ks * 16 + 2 * t;
                uint32_t af[4];
                af[0] = ldh2(ap);
                af[1] = ldh2(ap + 8 * GP);
                af[2] = ldh2(ap + 8);
                af[3] = ldh2(ap + 8 * GP + 8);
                #pragma unroll
                for (int nt = 0; nt < 4; nt++) mma16(acc[mt][nt], af, bfr[nt]);
            }
        }
        __syncthreads();
    }

    // Epilogue
    #pragma unroll
    for (int mt = 0; mt < 4; mt++) {
        const int r1 = m0 + wm0 + mt * 16 + g;
        const int r2 = r1 + 8;
        #pragma unroll
        for (int nt = 0; nt < 4; nt++) {
            const int ntile = n0 + wn0 + nt * 8;
            const int col = ntile + 2 * t;
            const float2 bb2 = *(const float2*)(bias + col);
            float v0 = acc[mt][nt][0] + bb2.x;
            float v1 = acc[mt][nt][1] + bb2.y;
            float v2 = acc[mt][nt][2] + bb2.x;
            float v3 = acc[mt][nt][3] + bb2.y;
            if (mode == 0) {
                const int proj = ntile >> 10;
                const int h    = (ntile >> 6) & 15;
                const int d    = (ntile & 63) + 2 * t;
                const int b1 = r1 >> 11, s1 = r1 & 2047;
                const int b2 = r2 >> 11, s2 = r2 & 2047;
                const int bh1 = b1 * 16 + h, bh2 = b2 * 16 + h;
                if (proj == 0) {
                    *(__half2*)(qo + ((size_t)bh1 * Sn + s1) * Dn + d) =
                        __floats2half2_rn(v0 * QSCALE, v1 * QSCALE);
                    *(__half2*)(qo + ((size_t)bh2 * Sn + s2) * Dn + d) =
                        __floats2half2_rn(v2 * QSCALE, v3 * QSCALE);
                } else if (proj == 1) {
                    *(__half2*)(ko + ((size_t)bh1 * Sn + s1) * Dn + d) = __floats2half2_rn(v0, v1);
                    *(__half2*)(ko + ((size_t)bh2 * Sn + s2) * Dn + d) = __floats2half2_rn(v2, v3);
                } else {
                    vo[((size_t)bh1 * Dn + d)     * Sn + s1] = __float2half_rn(v0);
                    vo[((size_t)bh1 * Dn + d + 1) * Sn + s1] = __float2half_rn(v1);
                    vo[((size_t)bh2 * Dn + d)     * Sn + s2] = __float2half_rn(v2);
                    vo[((size_t)bh2 * Dn + d + 1) * Sn + s2] = __float2half_rn(v3);
                }
            } else {
                *(float2*)(out + (size_t)r1 * En + col) = make_float2(v0, v1);
                *(float2*)(out + (size_t)r2 * En + col) = make_float2(v2, v3);
            }
        }
    }
}

// ---------------------------------------------------------------------------
// Causal flash attention: fp16 MMA, 2-stage K/V double buffer.
// 128 threads; Q tile 128 = 4 warps x 32 rows (2 mt of 16); KV chunk 64.
// Q fragments hoisted to registers (loaded once); fp16x2 exp2; ones-MMA sums.
// ---------------------------------------------------------------------------
__global__ __launch_bounds__(128) void attn_mma(__half* __restrict__ ctx)
{
    extern __shared__ __half sm[];
    __half* Qs = sm;                         // [128][72] (staging only)
    __half* Ks = sm + 128 * HPAD;            // 2 x [64][72] (rows = key)
    __half* Vt = sm + 128 * HPAD + 2 * KVH;  // 2 x [64][72] (rows = d)

    const int tid = threadIdx.x;
    const int w   = tid >> 5;
    const int L   = tid & 31;
    const int g   = L >> 2;
    const int t   = L & 3;

    const int bh = blockIdx.y;
    const int b  = bh >> 4;
    const int h  = bh & 15;
    const int i0 = (gridDim.x - 1 - blockIdx.x) * 128;

    const __half* Qp = g_Qh + (size_t)bh * Sn * Dn;
    const __half* Kp = g_Kh + (size_t)bh * Sn * Dn;
    const __half* Vp = g_Vth + (size_t)bh * Dn * Sn;

    const uint32_t sQ = smem_u32(Qs);
    const uint32_t sK = smem_u32(Ks);
    const uint32_t sV = smem_u32(Vt);

    auto issueKV = [&](int ch) {
        const uint32_t off = (uint32_t)(ch & 1) * (KVH * 2);
        const int j0 = ch * 64;
        #pragma unroll
        for (int it = 0; it < 4; it++) {     // K: 64 rows x 8 granules
            int idx = tid + it * 128;
            int r = idx >> 3, c8 = idx & 7;
            cp16(sK + off + (uint32_t)(r * HPAD + c8 * 8) * 2,
                 Kp + (size_t)(j0 + r) * Dn + c8 * 8);
        }
        #pragma unroll
        for (int it = 0; it < 4; it++) {     // V^T: 64 d-rows x 8 granules
            int idx = tid + it * 128;
            int r = idx >> 3, c8 = idx & 7;
            cp16(sV + off + (uint32_t)(r * HPAD + c8 * 8) * 2,
                 Vp + (size_t)r * Sn + j0 + c8 * 8);
        }
        CP_COMMIT();
    };

    // Stage Q (own commit group), then KV chunk 0
    #pragma unroll
    for (int it = 0; it < 8; it++) {
        int idx = tid + it * 128;
        int r = idx >> 3, c8 = idx & 7;
        cp16(sQ + (uint32_t)(r * HPAD + c8 * 8) * 2, Qp + (size_t)(i0 + r) * Dn + c8 * 8);
    }
    CP_COMMIT();
    issueKV(0);

    // Wait for Q (allow KV0 pending), then hoist Q fragments into registers
    CP_WAIT1();
    __syncthreads();

    const int qr0 = i0 + w * 32;

    uint32_t qa[2][4][4];                    // [mt][ks][reg] — loop-invariant
    #pragma unroll
    for (int mt = 0; mt < 2; mt++)
        #pragma unroll
        for (int ks = 0; ks < 4; ks++) {
            const __half* qp = Qs + (w * 32 + mt * 16 + g) * HPAD + ks * 16 + 2 * t;
            qa[mt][ks][0] = ldh2(qp);
            qa[mt][ks][1] = ldh2(qp + 8 * HPAD);
            qa[mt][ks][2] = ldh2(qp + 8);
            qa[mt][ks][3] = ldh2(qp + 8 * HPAD + 8);
        }

    float o[2][8][4] = {};
    float osum[2][4] = {};
    float mrow[2][2] = {{ -1e30f, -1e30f }, { -1e30f, -1e30f }};
    const uint32_t bones[2] = { ONES_H2, ONES_H2 };

    const int nch = i0 / 64 + 2;
    for (int ch = 0; ch < nch; ch++) {
        const int j0 = ch * 64;
        if (ch + 1 < nch) { issueKV(ch + 1); CP_WAIT1(); }
        else              { CP_WAIT0(); }
        __syncthreads();

        const __half* Kb = Ks + (ch & 1) * KVH;
        const __half* Vb = Vt + (ch & 1) * KVH;

        if (j0 <= qr0 + 31) {
            // ---- S = Q K^T (log2 domain) ----
            float sc[2][8][4] = {};
            #pragma unroll
            for (int ks = 0; ks < 4; ks++) {
                #pragma unroll
                for (int nt = 0; nt < 8; nt++) {
                    const __half* kp = Kb + (nt * 8 + g) * HPAD + ks * 16 + 2 * t;
                    uint32_t bb[2];
                    bb[0] = ldh2(kp);
                    bb[1] = ldh2(kp + 8);
                    mma16(sc[0][nt], qa[0][ks], bb);
                    mma16(sc[1][nt], qa[1][ks], bb);
                }
            }

            // ---- causal mask + online max ----
            float cr[2][2];
            #pragma unroll
            for (int mt = 0; mt < 2; mt++) {
                const int r0g = qr0 + mt * 16 + g;
                const int r1g = r0g + 8;
                const bool needmask = (j0 + 63 > qr0 + mt * 16);
                if (needmask) {
                    #pragma unroll
                    for (int nt = 0; nt < 8; nt++) {
                        const int c0 = j0 + nt * 8 + 2 * t;
                        if (c0     > r0g) sc[mt][nt][0] = -1e30f;
                        if (c0 + 1 > r0g) sc[mt][nt][1] = -1e30f;
                        if (c0     > r1g) sc[mt][nt][2] = -1e30f;
                        if (c0 + 1 > r1g) sc[mt][nt][3] = -1e30f;
                    }
                }

                float mx0 = -1e30f, mx1 = -1e30f;
                #pragma unroll
                for (int nt = 0; nt < 8; nt++) {
                    mx0 = fmaxf(mx0, fmaxf(sc[mt][nt][0], sc[mt][nt][1]));
                    mx1 = fmaxf(mx1, fmaxf(sc[mt][nt][2], sc[mt][nt][3]));
                }
                mx0 = fmaxf(mx0, __shfl_xor_sync(0xffffffffu, mx0, 1));
                mx0 = fmaxf(mx0, __shfl_xor_sync(0xffffffffu, mx0, 2));
                mx1 = fmaxf(mx1, __shfl_xor_sync(0xffffffffu, mx1, 1));
                mx1 = fmaxf(mx1, __shfl_xor_sync(0xffffffffu, mx1, 2));

                const float m0n = fmaxf(mrow[mt][0], mx0);
                const float m1n = fmaxf(mrow[mt][1], mx1);
                cr[mt][0] = exp2f(mrow[mt][0] - m0n);
                cr[mt][1] = exp2f(mrow[mt][1] - m1n);
                mrow[mt][0] = m0n;
                mrow[mt][1] = m1n;

                #pragma unroll
                for (int nt = 0; nt < 8; nt++) {
                    o[mt][nt][0] *= cr[mt][0]; o[mt][nt][1] *= cr[mt][0];
                    o[mt][nt][2] *= cr[mt][1]; o[mt][nt][3] *= cr[mt][1];
                }
                osum[mt][0] *= cr[mt][0]; osum[mt][1] *= cr[mt][0];
                osum[mt][2] *= cr[mt][1]; osum[mt][3] *= cr[mt][1];
            }

            // ---- P = exp2(S - m) into fp16 A-frags; O += P V; rowsum += P@1 ----
            #pragma unroll
            for (int ks = 0; ks < 4; ks++) {
                uint32_t pa[2][4];
                #pragma unroll
                for (int mt = 0; mt < 2; mt++) {
                    const float m0 = mrow[mt][0];
                    const float m1 = mrow[mt][1];
                    pa[mt][0] = ex2h2(sc[mt][2*ks][0]   - m0, sc[mt][2*ks][1]   - m0);
                    pa[mt][1] = ex2h2(sc[mt][2*ks][2]   - m1, sc[mt][2*ks][3]   - m1);
                    pa[mt][2] = ex2h2(sc[mt][2*ks+1][0] - m0, sc[mt][2*ks+1][1] - m0);
                    pa[mt][3] = ex2h2(sc[mt][2*ks+1][2] - m1, sc[mt][2*ks+1][3] - m1);
                }
                #pragma unroll
                for (int nt = 0; nt < 8; nt++) {
                    const __half* vp = Vb + (nt * 8 + g) * HPAD + ks * 16 + 2 * t;
                    uint32_t bb[2];
                    bb[0] = ldh2(vp);
                    bb[1] = ldh2(vp + 8);
                    mma16(o[0][nt], pa[0], bb);
                    mma16(o[1][nt], pa[1], bb);
                }
                mma16(osum[0], pa[0], bones);
                mma16(osum[1], pa[1], bones);
            }
        }
        __syncthreads();
    }

    // ---- epilogue ----
    #pragma unroll
    for (int mt = 0; mt < 2; mt++) {
        const float inv0 = 1.f / osum[mt][0];
        const float inv1 = 1.f / osum[mt][2];
        const int s0g = qr0 + mt * 16 + g;
        const int s1g = s0g + 8;
        #pragma unroll
        for (int nt = 0; nt < 8; nt++) {
            const int d = nt * 8 + 2 * t;
            *(__half2*)(ctx + ((size_t)b * Sn + s0g) * En + h * Dn + d) =
                __floats2half2_rn(o[mt][nt][0] * inv0, o[mt][nt][1] * inv0);
            *(__half2*)(ctx + ((size_t)b * Sn + s1g) * En + h * Dn + d) =
                __floats2half2_rn(o[mt][nt][2] * inv1, o[mt][nt][3] * inv1);
        }
    }
}

// ---------------------------------------------------------------------------
extern "C" void kernel_launch(void* const* d_in, const int* in_sizes, int n_in,
                              void* d_out, int out_size)
{
    const float* x  = (const float*)d_in[0];
    const float* Wq = (const float*)d_in[1];
    const float* bq = (const float*)d_in[2];
    const float* Wk = (const float*)d_in[3];
    const float* bk = (const float*)d_in[4];
    const float* Wv = (const float*)d_in[5];
    const float* bv = (const float*)d_in[6];
    const float* Wo = (const float*)d_in[7];
    const float* bo = (const float*)d_in[8];
    float* out = (float*)d_out;

    __half *qh, *kh, *vth, *ctxh, *xh, *wth, *woh;
    float *biasv;
    cudaGetSymbolAddress((void**)&qh, g_Qh);
    cudaGetSymbolAddress((void**)&kh, g_Kh);
    cudaGetSymbolAddress((void**)&vth, g_Vth);
    cudaGetSymbolAddress((void**)&ctxh, g_ctxh);
    cudaGetSymbolAddress((void**)&xh, g_xh);
    cudaGetSymbolAddress((void**)&wth, g_Wth);
    cudaGetSymbolAddress((void**)&woh, g_Woh);
    cudaGetSymbolAddress((void**)&biasv, g_bias);

    const int gemm_smem = 2 * (GBM + GBN) * GP * 2;          // 73728 B
    const int attn_smem = (128 * HPAD + 4 * 64 * HPAD) * 2;  // 55296 B
    cudaFuncSetAttribute(gemm_mma, cudaFuncAttributeMaxDynamicSharedMemorySize, gemm_smem);
    cudaFuncSetAttribute(attn_mma, cudaFuncAttributeMaxDynamicSharedMemorySize, attn_smem);

    prep_xw<<<(Mn * En + En * En) / 1024, 256>>>(x, Wo);
    prep_w <<<dim3(NTOT / 32, En / 32), 256>>>(Wq, bq, Wk, bk, Wv, bv);

    gemm_mma<<<dim3(Mn / GBM, NTOT / GBN), 256, gemm_smem>>>(
        xh, wth, biasv, qh, kh, vth, nullptr, 0);
    attn_mma<<<dim3(Sn / 128, BHn), 128, attn_smem>>>(ctxh);
    gemm_mma<<<dim3(Mn / GBM, En / GBN), 256, gemm_smem>>>(
        ctxh, woh, bo, nullptr, nullptr, nullptr, out, 1);
}